// round 1
// baseline (speedup 1.0000x reference)
#include <cuda_runtime.h>
#include <math.h>

// ---------------------------------------------------------------------------
// Problem constants
// ---------------------------------------------------------------------------
#define BATCH 8
#define ICH   256      // IN_CH (conv1 out channels)
#define NFC   128      // NF
#define NPIX  1024     // 32*32 spatial after conv
#define KCONV 4096     // 64 in-ch * 8 * 8
#define MROWS 8192     // BATCH * NPIX

// ---------------------------------------------------------------------------
// Device scratch (static; no allocations allowed)
// All activation tensors stored [b][n][c] (channel fastest) so every GEMM has
// contiguous global loads and coalesced epilogue stores.
// ---------------------------------------------------------------------------
__device__ float g_y   [BATCH * NPIX * ICH];   // conv1 output   [b][n][256]
__device__ float g_fai [BATCH * NPIX * NFC];   // [b][n][128]
__device__ float g_sit [BATCH * NPIX * NFC];
__device__ float g_gama[BATCH * NPIX * NFC];
__device__ float g_S   [BATCH * NPIX * NPIX];  // sigmoid scores [b][n][m]
__device__ float g_att [BATCH * NPIX * NFC];   // attention out  [b][n][128]

// ---------------------------------------------------------------------------
// Kernel 1: conv1 as implicit-GEMM + BN + ReLU
//   C[row][oc] = sum_k A[row][k] * W[oc][k]
//   row = b*1024 + oh*32 + ow (M=8192), oc (N=256), k = ic*64+kh*8+kw (K=4096)
//   A[row][k] = x[b][ic][oh*8+kh][ow*8+kw]
//   Epilogue: g_y[row*256 + oc] = relu(acc*s[oc] + bias[oc])
// Tiles: 64x64x16, 256 threads, 4x4 per thread.
// ---------------------------------------------------------------------------
__global__ __launch_bounds__(256)
void conv1_kernel(const float* __restrict__ x,
                  const float* __restrict__ w1,
                  const float* __restrict__ s,
                  const float* __restrict__ bias)
{
    __shared__ float As[16][68];
    __shared__ float Bs[16][68];

    const int m0 = blockIdx.x * 64;    // row tile
    const int n0 = blockIdx.y * 64;    // oc tile
    const int tid = threadIdx.x;
    const int tx = tid & 15;           // 0..15 -> 4 cols each
    const int ty = tid >> 4;           // 0..15 -> 4 rows each
    const int kk = tid & 15;           // k within tile (load phase)
    const int ms = tid >> 4;           // 0..15 (load phase)

    float acc[4][4] = {};

    for (int k0 = 0; k0 < KCONV; k0 += 16) {
        const int k  = k0 + kk;
        const int ic = k >> 6;
        const int kh = (k >> 3) & 7;
        const int kw = k & 7;
        #pragma unroll
        for (int i = 0; i < 4; i++) {
            const int row = m0 + ms + i * 16;
            const int b  = row >> 10;
            const int oh = (row >> 5) & 31;
            const int ow = row & 31;
            As[kk][ms + i * 16] =
                x[(((((b * 64 + ic) * 32 + oh) * 8 + kh) * 32 + ow) * 8 + kw)];
        }
        #pragma unroll
        for (int i = 0; i < 4; i++) {
            const int nn = ms + i * 16;
            Bs[kk][nn] = w1[(size_t)(n0 + nn) * KCONV + k];
        }
        __syncthreads();

        #pragma unroll
        for (int kq = 0; kq < 16; kq++) {
            const float4 a = *(const float4*)&As[kq][ty * 4];
            const float4 b = *(const float4*)&Bs[kq][tx * 4];
            acc[0][0] += a.x * b.x; acc[0][1] += a.x * b.y; acc[0][2] += a.x * b.z; acc[0][3] += a.x * b.w;
            acc[1][0] += a.y * b.x; acc[1][1] += a.y * b.y; acc[1][2] += a.y * b.z; acc[1][3] += a.y * b.w;
            acc[2][0] += a.z * b.x; acc[2][1] += a.z * b.y; acc[2][2] += a.z * b.z; acc[2][3] += a.z * b.w;
            acc[3][0] += a.w * b.x; acc[3][1] += a.w * b.y; acc[3][2] += a.w * b.z; acc[3][3] += a.w * b.w;
        }
        __syncthreads();
    }

    #pragma unroll
    for (int i = 0; i < 4; i++) {
        const int row = m0 + ty * 4 + i;
        #pragma unroll
        for (int j = 0; j < 4; j++) {
            const int oc = n0 + tx * 4 + j;
            const float v = acc[i][j] * s[oc] + bias[oc];
            g_y[(size_t)row * ICH + oc] = fmaxf(v, 0.0f);
        }
    }
}

// ---------------------------------------------------------------------------
// Kernel 2: fused 1x1 projections (fai / sit / gama), BN + ReLU
//   Per (b, proj): C[n][o] = sum_c Y[b][n][c] * W[o][c]
//   M = 1024 (n), N = 128 (o), K = 256 (c)
//   blockIdx.z encodes b*3 + proj
// ---------------------------------------------------------------------------
__global__ __launch_bounds__(256)
void proj_kernel(const float* __restrict__ w_fai, const float* __restrict__ sf, const float* __restrict__ bf,
                 const float* __restrict__ w_sit, const float* __restrict__ ss, const float* __restrict__ bs,
                 const float* __restrict__ w_gam, const float* __restrict__ sg, const float* __restrict__ bg)
{
    __shared__ float As[16][68];
    __shared__ float Bs[16][68];

    const int z    = blockIdx.z;
    const int b    = z / 3;
    const int proj = z % 3;
    const float* W;  const float* S;  const float* Bv;  float* outp;
    if (proj == 0)      { W = w_fai; S = sf; Bv = bf; outp = g_fai; }
    else if (proj == 1) { W = w_sit; S = ss; Bv = bs; outp = g_sit; }
    else                { W = w_gam; S = sg; Bv = bg; outp = g_gama; }

    const int m0 = blockIdx.x * 64;   // n tile
    const int n0 = blockIdx.y * 64;   // o tile
    const int tid = threadIdx.x;
    const int tx = tid & 15, ty = tid >> 4;
    const int kk = tid & 15, ms = tid >> 4;

    const float* Ybase = g_y + (size_t)b * NPIX * ICH;

    float acc[4][4] = {};

    for (int k0 = 0; k0 < ICH; k0 += 16) {
        #pragma unroll
        for (int i = 0; i < 4; i++) {
            const int mm = ms + i * 16;
            As[kk][mm] = Ybase[(size_t)(m0 + mm) * ICH + k0 + kk];
        }
        #pragma unroll
        for (int i = 0; i < 4; i++) {
            const int nn = ms + i * 16;
            Bs[kk][nn] = W[(size_t)(n0 + nn) * ICH + k0 + kk];
        }
        __syncthreads();
        #pragma unroll
        for (int kq = 0; kq < 16; kq++) {
            const float4 a = *(const float4*)&As[kq][ty * 4];
            const float4 bvec = *(const float4*)&Bs[kq][tx * 4];
            acc[0][0] += a.x * bvec.x; acc[0][1] += a.x * bvec.y; acc[0][2] += a.x * bvec.z; acc[0][3] += a.x * bvec.w;
            acc[1][0] += a.y * bvec.x; acc[1][1] += a.y * bvec.y; acc[1][2] += a.y * bvec.z; acc[1][3] += a.y * bvec.w;
            acc[2][0] += a.z * bvec.x; acc[2][1] += a.z * bvec.y; acc[2][2] += a.z * bvec.z; acc[2][3] += a.z * bvec.w;
            acc[3][0] += a.w * bvec.x; acc[3][1] += a.w * bvec.y; acc[3][2] += a.w * bvec.z; acc[3][3] += a.w * bvec.w;
        }
        __syncthreads();
    }

    float* obase = outp + (size_t)b * NPIX * NFC;
    #pragma unroll
    for (int i = 0; i < 4; i++) {
        const int n = m0 + ty * 4 + i;
        #pragma unroll
        for (int j = 0; j < 4; j++) {
            const int o = n0 + tx * 4 + j;
            const float v = acc[i][j] * S[o] + Bv[o];
            obase[(size_t)n * NFC + o] = fmaxf(v, 0.0f);
        }
    }
}

// ---------------------------------------------------------------------------
// Kernel 3: S[n][m] = sigmoid( sum_c fai[n][c] * sit[m][c] )   per batch
//   M = 1024 (n), N = 1024 (m), K = 128 (c)
// ---------------------------------------------------------------------------
__global__ __launch_bounds__(256)
void score_kernel()
{
    __shared__ float As[16][68];
    __shared__ float Bs[16][68];

    const int b  = blockIdx.z;
    const int m0 = blockIdx.x * 64;   // n tile
    const int n0 = blockIdx.y * 64;   // m tile
    const int tid = threadIdx.x;
    const int tx = tid & 15, ty = tid >> 4;
    const int kk = tid & 15, ms = tid >> 4;

    const float* F = g_fai + (size_t)b * NPIX * NFC;
    const float* T = g_sit + (size_t)b * NPIX * NFC;

    float acc[4][4] = {};

    for (int k0 = 0; k0 < NFC; k0 += 16) {
        #pragma unroll
        for (int i = 0; i < 4; i++) {
            const int mm = ms + i * 16;
            As[kk][mm] = F[(size_t)(m0 + mm) * NFC + k0 + kk];
        }
        #pragma unroll
        for (int i = 0; i < 4; i++) {
            const int nn = ms + i * 16;
            Bs[kk][nn] = T[(size_t)(n0 + nn) * NFC + k0 + kk];
        }
        __syncthreads();
        #pragma unroll
        for (int kq = 0; kq < 16; kq++) {
            const float4 a = *(const float4*)&As[kq][ty * 4];
            const float4 bvec = *(const float4*)&Bs[kq][tx * 4];
            acc[0][0] += a.x * bvec.x; acc[0][1] += a.x * bvec.y; acc[0][2] += a.x * bvec.z; acc[0][3] += a.x * bvec.w;
            acc[1][0] += a.y * bvec.x; acc[1][1] += a.y * bvec.y; acc[1][2] += a.y * bvec.z; acc[1][3] += a.y * bvec.w;
            acc[2][0] += a.z * bvec.x; acc[2][1] += a.z * bvec.y; acc[2][2] += a.z * bvec.z; acc[2][3] += a.z * bvec.w;
            acc[3][0] += a.w * bvec.x; acc[3][1] += a.w * bvec.y; acc[3][2] += a.w * bvec.z; acc[3][3] += a.w * bvec.w;
        }
        __syncthreads();
    }

    float* Sout = g_S + (size_t)b * NPIX * NPIX;
    #pragma unroll
    for (int i = 0; i < 4; i++) {
        const int n = m0 + ty * 4 + i;
        #pragma unroll
        for (int j = 0; j < 4; j++) {
            const int m = n0 + tx * 4 + j;
            const float v = acc[i][j];
            Sout[(size_t)n * NPIX + m] = 1.0f / (1.0f + expf(-v));
        }
    }
}

// ---------------------------------------------------------------------------
// Kernel 4: att[n][c] = sum_m S[n][m] * gama[m][c]   per batch
//   M = 1024 (n), N = 128 (c), K = 1024 (m)
// ---------------------------------------------------------------------------
__global__ __launch_bounds__(256)
void attn_out_kernel()
{
    __shared__ float As[16][68];
    __shared__ float Bs[16][68];

    const int b  = blockIdx.z;
    const int m0 = blockIdx.x * 64;   // n tile
    const int n0 = blockIdx.y * 64;   // c tile
    const int tid = threadIdx.x;
    const int tx = tid & 15, ty = tid >> 4;
    const int kka = tid & 15, msa = tid >> 4;     // A-load mapping
    const int nnb = tid & 63, kkb = tid >> 6;     // B-load mapping (coalesced over c)

    const float* Smat = g_S    + (size_t)b * NPIX * NPIX;
    const float* G    = g_gama + (size_t)b * NPIX * NFC;

    float acc[4][4] = {};

    for (int k0 = 0; k0 < NPIX; k0 += 16) {
        #pragma unroll
        for (int i = 0; i < 4; i++) {
            const int mm = msa + i * 16;
            As[kka][mm] = Smat[(size_t)(m0 + mm) * NPIX + k0 + kka];
        }
        #pragma unroll
        for (int i = 0; i < 4; i++) {
            const int kq = kkb + i * 4;
            Bs[kq][nnb] = G[(size_t)(k0 + kq) * NFC + n0 + nnb];
        }
        __syncthreads();
        #pragma unroll
        for (int kq = 0; kq < 16; kq++) {
            const float4 a = *(const float4*)&As[kq][ty * 4];
            const float4 bvec = *(const float4*)&Bs[kq][tx * 4];
            acc[0][0] += a.x * bvec.x; acc[0][1] += a.x * bvec.y; acc[0][2] += a.x * bvec.z; acc[0][3] += a.x * bvec.w;
            acc[1][0] += a.y * bvec.x; acc[1][1] += a.y * bvec.y; acc[1][2] += a.y * bvec.z; acc[1][3] += a.y * bvec.w;
            acc[2][0] += a.z * bvec.x; acc[2][1] += a.z * bvec.y; acc[2][2] += a.z * bvec.z; acc[2][3] += a.z * bvec.w;
            acc[3][0] += a.w * bvec.x; acc[3][1] += a.w * bvec.y; acc[3][2] += a.w * bvec.z; acc[3][3] += a.w * bvec.w;
        }
        __syncthreads();
    }

    float* obase = g_att + (size_t)b * NPIX * NFC;
    #pragma unroll
    for (int i = 0; i < 4; i++) {
        const int n = m0 + ty * 4 + i;
        #pragma unroll
        for (int j = 0; j < 4; j++) {
            const int c = n0 + tx * 4 + j;
            obase[(size_t)n * NFC + c] = acc[i][j];
        }
    }
}

// ---------------------------------------------------------------------------
// Kernel 5: bilinear upsample x8, align_corners=True
//   att [b][n=32*32][c=128]  ->  out [b][c][256][256]
// ---------------------------------------------------------------------------
__global__ __launch_bounds__(256)
void upsample_kernel(float* __restrict__ out)
{
    const long long idx = (long long)blockIdx.x * blockDim.x + threadIdx.x;
    const int xo = (int)(idx & 255);
    const int yo = (int)((idx >> 8) & 255);
    const int c  = (int)((idx >> 16) & 127);
    const int b  = (int)(idx >> 23);

    const float sc = (float)(31.0 / 255.0);
    const float ysf = (float)yo * sc;
    const float xsf = (float)xo * sc;
    int y0 = (int)floorf(ysf);
    int x0 = (int)floorf(xsf);
    const float wy = ysf - (float)y0;
    const float wx = xsf - (float)x0;
    const int y1 = min(y0 + 1, 31);
    const int x1 = min(x0 + 1, 31);

    const float* base = g_att + (size_t)b * NPIX * NFC;
    const float v00 = base[(size_t)(y0 * 32 + x0) * NFC + c];
    const float v10 = base[(size_t)(y1 * 32 + x0) * NFC + c];
    const float v01 = base[(size_t)(y0 * 32 + x1) * NFC + c];
    const float v11 = base[(size_t)(y1 * 32 + x1) * NFC + c];

    const float top0 = v00 * (1.0f - wy) + v10 * wy;
    const float top1 = v01 * (1.0f - wy) + v11 * wy;
    out[idx] = top0 * (1.0f - wx) + top1 * wx;
}

// ---------------------------------------------------------------------------
// Launch
// ---------------------------------------------------------------------------
extern "C" void kernel_launch(void* const* d_in, const int* in_sizes, int n_in,
                              void* d_out, int out_size)
{
    const float* x     = (const float*)d_in[0];
    const float* w1    = (const float*)d_in[1];
    const float* bn1_s = (const float*)d_in[2];
    const float* bn1_b = (const float*)d_in[3];
    const float* w_fai = (const float*)d_in[4];
    const float* bnf_s = (const float*)d_in[5];
    const float* bnf_b = (const float*)d_in[6];
    const float* w_sit = (const float*)d_in[7];
    const float* bns_s = (const float*)d_in[8];
    const float* bns_b = (const float*)d_in[9];
    const float* w_gam = (const float*)d_in[10];
    const float* bng_s = (const float*)d_in[11];
    const float* bng_b = (const float*)d_in[12];
    float* out = (float*)d_out;

    // 1. conv1 + BN + ReLU  (M=8192, N=256, K=4096)
    {
        dim3 grid(MROWS / 64, ICH / 64);
        conv1_kernel<<<grid, 256>>>(x, w1, bn1_s, bn1_b);
    }
    // 2. three 1x1 projections + BN + ReLU
    {
        dim3 grid(NPIX / 64, NFC / 64, BATCH * 3);
        proj_kernel<<<grid, 256>>>(w_fai, bnf_s, bnf_b,
                                   w_sit, bns_s, bns_b,
                                   w_gam, bng_s, bng_b);
    }
    // 3. S = sigmoid(fai^T sit)
    {
        dim3 grid(NPIX / 64, NPIX / 64, BATCH);
        score_kernel<<<grid, 256>>>();
    }
    // 4. att = S @ gama^T
    {
        dim3 grid(NPIX / 64, NFC / 64, BATCH);
        attn_out_kernel<<<grid, 256>>>();
    }
    // 5. bilinear upsample x8
    {
        const long long total = (long long)BATCH * NFC * 256 * 256;
        upsample_kernel<<<(unsigned)(total / 256), 256>>>(out);
    }
}

// round 3
// speedup vs baseline: 1.6926x; 1.6926x over previous
#include <cuda_runtime.h>
#include <cuda_bf16.h>
#include <math.h>
#include <stdint.h>

// ---------------------------------------------------------------------------
// Problem constants
// ---------------------------------------------------------------------------
#define BATCH 8
#define ICH   256
#define NFC   128
#define NPIX  1024
#define KCONV 4096
#define MROWS 8192

// ---------------------------------------------------------------------------
// Device scratch
// ---------------------------------------------------------------------------
__device__ float g_y   [BATCH * NPIX * ICH];
__device__ float g_fai [BATCH * NPIX * NFC];
__device__ float g_sit [BATCH * NPIX * NFC];
__device__ float g_gama[BATCH * NPIX * NFC];
__device__ float g_S   [BATCH * NPIX * NPIX];
__device__ float g_att [BATCH * NPIX * NFC];

// ---------------------------------------------------------------------------
// Portable warp-MMA helpers (valid on base sm_103 — no 'a' features)
// ---------------------------------------------------------------------------
__device__ __forceinline__ uint32_t smem_u32(const void* p) {
    uint32_t a;
    asm("{ .reg .u64 t; cvta.to.shared.u64 t, %1; cvt.u32.u64 %0, t; }" : "=r"(a) : "l"(p));
    return a;
}

__device__ __forceinline__ void ldsm_x4(uint32_t& r0, uint32_t& r1, uint32_t& r2, uint32_t& r3,
                                        uint32_t addr) {
    asm volatile("ldmatrix.sync.aligned.m8n8.x4.shared.b16 {%0,%1,%2,%3}, [%4];"
        : "=r"(r0), "=r"(r1), "=r"(r2), "=r"(r3) : "r"(addr));
}

__device__ __forceinline__ void mma_bf16(float* c, uint32_t a0, uint32_t a1, uint32_t a2, uint32_t a3,
                                         uint32_t b0, uint32_t b1) {
    asm volatile(
        "mma.sync.aligned.m16n8k16.row.col.f32.bf16.bf16.f32 "
        "{%0,%1,%2,%3}, {%4,%5,%6,%7}, {%8,%9}, {%0,%1,%2,%3};"
        : "+f"(c[0]), "+f"(c[1]), "+f"(c[2]), "+f"(c[3])
        : "r"(a0), "r"(a1), "r"(a2), "r"(a3), "r"(b0), "r"(b1));
}

__device__ __forceinline__ uint2 split_pack_hi(float4 v, float4& rem) {
    __nv_bfloat16 h0 = __float2bfloat16_rn(v.x), h1 = __float2bfloat16_rn(v.y);
    __nv_bfloat16 h2 = __float2bfloat16_rn(v.z), h3 = __float2bfloat16_rn(v.w);
    rem.x = v.x - __bfloat162float(h0);
    rem.y = v.y - __bfloat162float(h1);
    rem.z = v.z - __bfloat162float(h2);
    rem.w = v.w - __bfloat162float(h3);
    uint2 p;
    p.x = (uint32_t)__bfloat16_as_ushort(h0) | ((uint32_t)__bfloat16_as_ushort(h1) << 16);
    p.y = (uint32_t)__bfloat16_as_ushort(h2) | ((uint32_t)__bfloat16_as_ushort(h3) << 16);
    return p;
}
__device__ __forceinline__ uint2 pack_lo(float4 rem) {
    __nv_bfloat16 l0 = __float2bfloat16_rn(rem.x), l1 = __float2bfloat16_rn(rem.y);
    __nv_bfloat16 l2 = __float2bfloat16_rn(rem.z), l3 = __float2bfloat16_rn(rem.w);
    uint2 p;
    p.x = (uint32_t)__bfloat16_as_ushort(l0) | ((uint32_t)__bfloat16_as_ushort(l1) << 16);
    p.y = (uint32_t)__bfloat16_as_ushort(l2) | ((uint32_t)__bfloat16_as_ushort(l3) << 16);
    return p;
}

// ---------------------------------------------------------------------------
// Kernel 1: conv1 implicit GEMM (M=8192, N=256, K=4096) via mma.sync bf16
//   with hi/lo split: D += Ah*Bh + Al*Bh + Ah*Bl  (emulated fp32, ~1e-5 rel)
// CTA tile 128x128, K-tile 32, 8 warps (warp tile 32x64), double-buffered.
// SMEM per stage: Ahi/Alo/Bhi/Blo each 128 rows x 32 bf16, row stride 80B.
// ---------------------------------------------------------------------------
#define RSTRIDE 80
#define MAT_BYTES (128 * RSTRIDE)            // 10240
#define STAGE_BYTES (4 * MAT_BYTES)          // 40960
#define CONV_SMEM (2 * STAGE_BYTES)          // 81920

__global__ __launch_bounds__(256, 1)
void conv1_mma_kernel(const float* __restrict__ x,
                      const float* __restrict__ w1,
                      const float* __restrict__ bnS,
                      const float* __restrict__ bnB)
{
    extern __shared__ char smem[];
    const uint32_t sbase = smem_u32(smem);

    const int tid = threadIdx.x;
    const int wid = tid >> 5;
    const int l   = tid & 31;
    const int warp_m = wid & 3;        // 4 warps in M (32 rows each)
    const int warp_n = wid >> 2;       // 2 warps in N (64 cols each)
    const int m0 = blockIdx.x * 128;
    const int n0 = blockIdx.y * 128;

    // load-phase mapping: each thread: 4 float4 for A, 4 for B per k-tile
    const int lr = tid >> 1;                   // 0..127 (row)
    const int lq2 = (tid & 1) * 2;             // first quad index (0 or 2) ; +4 stride j

    float acc[2][8][4];
    #pragma unroll
    for (int i = 0; i < 2; i++)
        #pragma unroll
        for (int j = 0; j < 8; j++)
            #pragma unroll
            for (int k = 0; k < 4; k++) acc[i][j][k] = 0.0f;

    float4 apf[4], bpf[4];

    // ---- global load of k-tile kt into registers ----
    auto gload = [&](int kt) {
        const int kb = kt * 32;
        #pragma unroll
        for (int j = 0; j < 4; j++) {
            // f = tid*? mapping: r = lr, q = lq2 + (j&1) + (j>>1)*4  -> covers q 0..7 over 2 threads x 4 j
            const int q = lq2 + (j & 1) + ((j >> 1) << 2);
            const int k = kb + q * 4;
            const int rowA = m0 + lr;
            const int b  = rowA >> 10, oh = (rowA >> 5) & 31, ow = rowA & 31;
            const int ic = k >> 6, kh = (k >> 3) & 7, kw = k & 7;
            apf[j] = *(const float4*)&x[((size_t)(b * 64 + ic) * 256 + (oh * 8 + kh)) * 256 + (ow * 8 + kw)];
            bpf[j] = *(const float4*)&w1[(size_t)(n0 + lr) * KCONV + k];
        }
    };

    // ---- convert + store registers into smem stage ----
    auto sstore = [&](int stage) {
        char* sb = smem + stage * STAGE_BYTES;
        #pragma unroll
        for (int j = 0; j < 4; j++) {
            const int q = lq2 + (j & 1) + ((j >> 1) << 2);
            const uint32_t off = (uint32_t)(lr * RSTRIDE + q * 8);
            float4 rem;
            uint2 ph = split_pack_hi(apf[j], rem);
            *(uint2*)(sb + off) = ph;                       // Ahi
            *(uint2*)(sb + MAT_BYTES + off) = pack_lo(rem); // Alo
            ph = split_pack_hi(bpf[j], rem);
            *(uint2*)(sb + 2 * MAT_BYTES + off) = ph;       // Bhi
            *(uint2*)(sb + 3 * MAT_BYTES + off) = pack_lo(rem); // Blo
        }
    };

    // ldmatrix base addresses for this lane
    const uint32_t a_row = (uint32_t)(warp_m * 32 + (l & 15));
    const uint32_t a_coff = (uint32_t)((l >> 4) << 4);
    const uint32_t b_row = (uint32_t)(warp_n * 64 + (l & 7) + ((l >> 4) & 1) * 8);
    const uint32_t b_coff = (uint32_t)(((l >> 3) & 1) << 4);

    gload(0);
    sstore(0);
    __syncthreads();

    const int KT = KCONV / 32;   // 128
    for (int kt = 0; kt < KT; ++kt) {
        if (kt < KT - 1) gload(kt + 1);

        const uint32_t st = sbase + (uint32_t)((kt & 1) * STAGE_BYTES);
        #pragma unroll
        for (int ks = 0; ks < 2; ++ks) {
            uint32_t ah[2][4], al[2][4];
            #pragma unroll
            for (int bm = 0; bm < 2; ++bm) {
                const uint32_t aaddr = st + (a_row + bm * 16) * RSTRIDE + ks * 32 + a_coff;
                ldsm_x4(ah[bm][0], ah[bm][1], ah[bm][2], ah[bm][3], aaddr);
                ldsm_x4(al[bm][0], al[bm][1], al[bm][2], al[bm][3], aaddr + MAT_BYTES);
            }
            #pragma unroll
            for (int np = 0; np < 4; ++np) {
                uint32_t bh[4], bl[4];
                const uint32_t baddr = st + 2 * MAT_BYTES + (b_row + np * 16) * RSTRIDE + ks * 32 + b_coff;
                ldsm_x4(bh[0], bh[1], bh[2], bh[3], baddr);
                ldsm_x4(bl[0], bl[1], bl[2], bl[3], baddr + MAT_BYTES);
                #pragma unroll
                for (int bm = 0; bm < 2; ++bm) {
                    mma_bf16(acc[bm][np * 2],     ah[bm][0], ah[bm][1], ah[bm][2], ah[bm][3], bh[0], bh[1]);
                    mma_bf16(acc[bm][np * 2],     al[bm][0], al[bm][1], al[bm][2], al[bm][3], bh[0], bh[1]);
                    mma_bf16(acc[bm][np * 2],     ah[bm][0], ah[bm][1], ah[bm][2], ah[bm][3], bl[0], bl[1]);
                    mma_bf16(acc[bm][np * 2 + 1], ah[bm][0], ah[bm][1], ah[bm][2], ah[bm][3], bh[2], bh[3]);
                    mma_bf16(acc[bm][np * 2 + 1], al[bm][0], al[bm][1], al[bm][2], al[bm][3], bh[2], bh[3]);
                    mma_bf16(acc[bm][np * 2 + 1], ah[bm][0], ah[bm][1], ah[bm][2], ah[bm][3], bl[2], bl[3]);
                }
            }
        }

        if (kt < KT - 1) sstore((kt + 1) & 1);
        __syncthreads();
    }

    // ---- epilogue: BN + ReLU, write g_y ----
    const int erow0 = m0 + warp_m * 32 + (l >> 2);
    const int ecol0 = n0 + warp_n * 64 + (l & 3) * 2;
    #pragma unroll
    for (int bm = 0; bm < 2; ++bm) {
        #pragma unroll
        for (int nb = 0; nb < 8; ++nb) {
            const int col = ecol0 + nb * 8;
            const float s0 = bnS[col], s1 = bnS[col + 1];
            const float v0 = bnB[col], v1 = bnB[col + 1];
            const int r0 = erow0 + bm * 16;
            float2 o0, o1;
            o0.x = fmaxf(acc[bm][nb][0] * s0 + v0, 0.0f);
            o0.y = fmaxf(acc[bm][nb][1] * s1 + v1, 0.0f);
            o1.x = fmaxf(acc[bm][nb][2] * s0 + v0, 0.0f);
            o1.y = fmaxf(acc[bm][nb][3] * s1 + v1, 0.0f);
            *(float2*)&g_y[(size_t)r0 * ICH + col] = o0;
            *(float2*)&g_y[(size_t)(r0 + 8) * ICH + col] = o1;
        }
    }
}

// ---------------------------------------------------------------------------
// Kernel 2: fused 1x1 projections (fai / sit / gama), BN + ReLU  (fp32 SIMT)
// ---------------------------------------------------------------------------
__global__ __launch_bounds__(256)
void proj_kernel(const float* __restrict__ w_fai, const float* __restrict__ sf, const float* __restrict__ bf,
                 const float* __restrict__ w_sit, const float* __restrict__ ss, const float* __restrict__ bs,
                 const float* __restrict__ w_gam, const float* __restrict__ sg, const float* __restrict__ bg)
{
    __shared__ float As[16][68];
    __shared__ float Bs[16][68];

    const int z    = blockIdx.z;
    const int b    = z / 3;
    const int proj = z % 3;
    const float* W;  const float* S;  const float* Bv;  float* outp;
    if (proj == 0)      { W = w_fai; S = sf; Bv = bf; outp = g_fai; }
    else if (proj == 1) { W = w_sit; S = ss; Bv = bs; outp = g_sit; }
    else                { W = w_gam; S = sg; Bv = bg; outp = g_gama; }

    const int m0 = blockIdx.x * 64;
    const int n0 = blockIdx.y * 64;
    const int tid = threadIdx.x;
    const int tx = tid & 15, ty = tid >> 4;
    const int kk = tid & 15, ms = tid >> 4;

    const float* Ybase = g_y + (size_t)b * NPIX * ICH;

    float acc[4][4] = {};

    for (int k0 = 0; k0 < ICH; k0 += 16) {
        #pragma unroll
        for (int i = 0; i < 4; i++) {
            const int mm = ms + i * 16;
            As[kk][mm] = Ybase[(size_t)(m0 + mm) * ICH + k0 + kk];
        }
        #pragma unroll
        for (int i = 0; i < 4; i++) {
            const int nn = ms + i * 16;
            Bs[kk][nn] = W[(size_t)(n0 + nn) * ICH + k0 + kk];
        }
        __syncthreads();
        #pragma unroll
        for (int kq = 0; kq < 16; kq++) {
            const float4 a = *(const float4*)&As[kq][ty * 4];
            const float4 bvec = *(const float4*)&Bs[kq][tx * 4];
            acc[0][0] += a.x * bvec.x; acc[0][1] += a.x * bvec.y; acc[0][2] += a.x * bvec.z; acc[0][3] += a.x * bvec.w;
            acc[1][0] += a.y * bvec.x; acc[1][1] += a.y * bvec.y; acc[1][2] += a.y * bvec.z; acc[1][3] += a.y * bvec.w;
            acc[2][0] += a.z * bvec.x; acc[2][1] += a.z * bvec.y; acc[2][2] += a.z * bvec.z; acc[2][3] += a.z * bvec.w;
            acc[3][0] += a.w * bvec.x; acc[3][1] += a.w * bvec.y; acc[3][2] += a.w * bvec.z; acc[3][3] += a.w * bvec.w;
        }
        __syncthreads();
    }

    float* obase = outp + (size_t)b * NPIX * NFC;
    #pragma unroll
    for (int i = 0; i < 4; i++) {
        const int n = m0 + ty * 4 + i;
        #pragma unroll
        for (int j = 0; j < 4; j++) {
            const int o = n0 + tx * 4 + j;
            const float v = acc[i][j] * S[o] + Bv[o];
            obase[(size_t)n * NFC + o] = fmaxf(v, 0.0f);
        }
    }
}

// ---------------------------------------------------------------------------
// Kernel 3: S[n][m] = sigmoid( fai[n] . sit[m] )  per batch  (fp32 SIMT)
// ---------------------------------------------------------------------------
__global__ __launch_bounds__(256)
void score_kernel()
{
    __shared__ float As[16][68];
    __shared__ float Bs[16][68];

    const int b  = blockIdx.z;
    const int m0 = blockIdx.x * 64;
    const int n0 = blockIdx.y * 64;
    const int tid = threadIdx.x;
    const int tx = tid & 15, ty = tid >> 4;
    const int kk = tid & 15, ms = tid >> 4;

    const float* F = g_fai + (size_t)b * NPIX * NFC;
    const float* T = g_sit + (size_t)b * NPIX * NFC;

    float acc[4][4] = {};

    for (int k0 = 0; k0 < NFC; k0 += 16) {
        #pragma unroll
        for (int i = 0; i < 4; i++) {
            const int mm = ms + i * 16;
            As[kk][mm] = F[(size_t)(m0 + mm) * NFC + k0 + kk];
        }
        #pragma unroll
        for (int i = 0; i < 4; i++) {
            const int nn = ms + i * 16;
            Bs[kk][nn] = T[(size_t)(n0 + nn) * NFC + k0 + kk];
        }
        __syncthreads();
        #pragma unroll
        for (int kq = 0; kq < 16; kq++) {
            const float4 a = *(const float4*)&As[kq][ty * 4];
            const float4 bvec = *(const float4*)&Bs[kq][tx * 4];
            acc[0][0] += a.x * bvec.x; acc[0][1] += a.x * bvec.y; acc[0][2] += a.x * bvec.z; acc[0][3] += a.x * bvec.w;
            acc[1][0] += a.y * bvec.x; acc[1][1] += a.y * bvec.y; acc[1][2] += a.y * bvec.z; acc[1][3] += a.y * bvec.w;
            acc[2][0] += a.z * bvec.x; acc[2][1] += a.z * bvec.y; acc[2][2] += a.z * bvec.z; acc[2][3] += a.z * bvec.w;
            acc[3][0] += a.w * bvec.x; acc[3][1] += a.w * bvec.y; acc[3][2] += a.w * bvec.z; acc[3][3] += a.w * bvec.w;
        }
        __syncthreads();
    }

    float* Sout = g_S + (size_t)b * NPIX * NPIX;
    #pragma unroll
    for (int i = 0; i < 4; i++) {
        const int n = m0 + ty * 4 + i;
        #pragma unroll
        for (int j = 0; j < 4; j++) {
            const int m = n0 + tx * 4 + j;
            Sout[(size_t)n * NPIX + m] = 1.0f / (1.0f + expf(-acc[i][j]));
        }
    }
}

// ---------------------------------------------------------------------------
// Kernel 4: att[n][c] = sum_m S[n][m] * gama[m][c]   per batch  (fp32 SIMT)
// ---------------------------------------------------------------------------
__global__ __launch_bounds__(256)
void attn_out_kernel()
{
    __shared__ float As[16][68];
    __shared__ float Bs[16][68];

    const int b  = blockIdx.z;
    const int m0 = blockIdx.x * 64;
    const int n0 = blockIdx.y * 64;
    const int tid = threadIdx.x;
    const int tx = tid & 15, ty = tid >> 4;
    const int kka = tid & 15, msa = tid >> 4;
    const int nnb = tid & 63, kkb = tid >> 6;

    const float* Smat = g_S    + (size_t)b * NPIX * NPIX;
    const float* G    = g_gama + (size_t)b * NPIX * NFC;

    float acc[4][4] = {};

    for (int k0 = 0; k0 < NPIX; k0 += 16) {
        #pragma unroll
        for (int i = 0; i < 4; i++) {
            const int mm = msa + i * 16;
            As[kka][mm] = Smat[(size_t)(m0 + mm) * NPIX + k0 + kka];
        }
        #pragma unroll
        for (int i = 0; i < 4; i++) {
            const int kq = kkb + i * 4;
            Bs[kq][nnb] = G[(size_t)(k0 + kq) * NFC + n0 + nnb];
        }
        __syncthreads();
        #pragma unroll
        for (int kq = 0; kq < 16; kq++) {
            const float4 a = *(const float4*)&As[kq][ty * 4];
            const float4 bvec = *(const float4*)&Bs[kq][tx * 4];
            acc[0][0] += a.x * bvec.x; acc[0][1] += a.x * bvec.y; acc[0][2] += a.x * bvec.z; acc[0][3] += a.x * bvec.w;
            acc[1][0] += a.y * bvec.x; acc[1][1] += a.y * bvec.y; acc[1][2] += a.y * bvec.z; acc[1][3] += a.y * bvec.w;
            acc[2][0] += a.z * bvec.x; acc[2][1] += a.z * bvec.y; acc[2][2] += a.z * bvec.z; acc[2][3] += a.z * bvec.w;
            acc[3][0] += a.w * bvec.x; acc[3][1] += a.w * bvec.y; acc[3][2] += a.w * bvec.z; acc[3][3] += a.w * bvec.w;
        }
        __syncthreads();
    }

    float* obase = g_att + (size_t)b * NPIX * NFC;
    #pragma unroll
    for (int i = 0; i < 4; i++) {
        const int n = m0 + ty * 4 + i;
        #pragma unroll
        for (int j = 0; j < 4; j++) {
            const int c = n0 + tx * 4 + j;
            obase[(size_t)n * NFC + c] = acc[i][j];
        }
    }
}

// ---------------------------------------------------------------------------
// Kernel 5: bilinear upsample x8, align_corners=True
// ---------------------------------------------------------------------------
__global__ __launch_bounds__(256)
void upsample_kernel(float* __restrict__ out)
{
    const long long idx = (long long)blockIdx.x * blockDim.x + threadIdx.x;
    const int xo = (int)(idx & 255);
    const int yo = (int)((idx >> 8) & 255);
    const int c  = (int)((idx >> 16) & 127);
    const int b  = (int)(idx >> 23);

    const float sc = (float)(31.0 / 255.0);
    const float ysf = (float)yo * sc;
    const float xsf = (float)xo * sc;
    int y0 = (int)floorf(ysf);
    int x0 = (int)floorf(xsf);
    const float wy = ysf - (float)y0;
    const float wx = xsf - (float)x0;
    const int y1 = min(y0 + 1, 31);
    const int x1 = min(x0 + 1, 31);

    const float* base = g_att + (size_t)b * NPIX * NFC;
    const float v00 = base[(size_t)(y0 * 32 + x0) * NFC + c];
    const float v10 = base[(size_t)(y1 * 32 + x0) * NFC + c];
    const float v01 = base[(size_t)(y0 * 32 + x1) * NFC + c];
    const float v11 = base[(size_t)(y1 * 32 + x1) * NFC + c];

    const float top0 = v00 * (1.0f - wy) + v10 * wy;
    const float top1 = v01 * (1.0f - wy) + v11 * wy;
    out[idx] = top0 * (1.0f - wx) + top1 * wx;
}

// ---------------------------------------------------------------------------
// Launch
// ---------------------------------------------------------------------------
extern "C" void kernel_launch(void* const* d_in, const int* in_sizes, int n_in,
                              void* d_out, int out_size)
{
    const float* x     = (const float*)d_in[0];
    const float* w1    = (const float*)d_in[1];
    const float* bn1_s = (const float*)d_in[2];
    const float* bn1_b = (const float*)d_in[3];
    const float* w_fai = (const float*)d_in[4];
    const float* bnf_s = (const float*)d_in[5];
    const float* bnf_b = (const float*)d_in[6];
    const float* w_sit = (const float*)d_in[7];
    const float* bns_s = (const float*)d_in[8];
    const float* bns_b = (const float*)d_in[9];
    const float* w_gam = (const float*)d_in[10];
    const float* bng_s = (const float*)d_in[11];
    const float* bng_b = (const float*)d_in[12];
    float* out = (float*)d_out;

    // 1. conv1 + BN + ReLU via mma.sync bf16 hi/lo split
    {
        cudaFuncSetAttribute(conv1_mma_kernel,
                             cudaFuncAttributeMaxDynamicSharedMemorySize, CONV_SMEM);
        dim3 grid(MROWS / 128, ICH / 128);
        conv1_mma_kernel<<<grid, 256, CONV_SMEM>>>(x, w1, bn1_s, bn1_b);
    }
    // 2. three 1x1 projections + BN + ReLU
    {
        dim3 grid(NPIX / 64, NFC / 64, BATCH * 3);
        proj_kernel<<<grid, 256>>>(w_fai, bnf_s, bnf_b,
                                   w_sit, bns_s, bns_b,
                                   w_gam, bng_s, bng_b);
    }
    // 3. S = sigmoid(fai^T sit)
    {
        dim3 grid(NPIX / 64, NPIX / 64, BATCH);
        score_kernel<<<grid, 256>>>();
    }
    // 4. att = S @ gama^T
    {
        dim3 grid(NPIX / 64, NFC / 64, BATCH);
        attn_out_kernel<<<grid, 256>>>();
    }
    // 5. bilinear upsample x8
    {
        const long long total = (long long)BATCH * NFC * 256 * 256;
        upsample_kernel<<<(unsigned)(total / 256), 256>>>(out);
    }
}

// round 4
// speedup vs baseline: 2.0830x; 1.2307x over previous
#include <cuda_runtime.h>
#include <cuda_bf16.h>
#include <math.h>
#include <stdint.h>

// ---------------------------------------------------------------------------
// Problem constants
// ---------------------------------------------------------------------------
#define BATCH 8
#define ICH   256
#define NFC   128
#define NPIX  1024
#define KCONV 4096
#define MROWS 8192

// ---------------------------------------------------------------------------
// Device scratch (bf16 hi/lo split pairs throughout the GEMM chain)
// ---------------------------------------------------------------------------
__device__ __nv_bfloat16 g_w1h[ICH * KCONV], g_w1l[ICH * KCONV];
__device__ __nv_bfloat16 g_wfh[NFC * ICH],  g_wfl[NFC * ICH];
__device__ __nv_bfloat16 g_wsh[NFC * ICH],  g_wsl[NFC * ICH];
__device__ __nv_bfloat16 g_wgh[NFC * ICH],  g_wgl[NFC * ICH];

__device__ __nv_bfloat16 g_yh[MROWS * ICH],  g_yl[MROWS * ICH];            // conv out [row][256]
__device__ __nv_bfloat16 g_faih[BATCH * NPIX * NFC], g_fail_[BATCH * NPIX * NFC]; // [b][n][128]
__device__ __nv_bfloat16 g_sith[BATCH * NPIX * NFC], g_sitl[BATCH * NPIX * NFC];
__device__ __nv_bfloat16 g_gTh[BATCH * NFC * NPIX],  g_gTl[BATCH * NFC * NPIX];   // [b][c][m]
__device__ __nv_bfloat16 g_Sh[BATCH * NPIX * NPIX],  g_Sl[BATCH * NPIX * NPIX];   // [b][n][m]
__device__ float g_att[BATCH * NPIX * NFC];                                        // [b][n][128]

// ---------------------------------------------------------------------------
// Portable warp-MMA helpers (base sm_103, no 'a' features)
// ---------------------------------------------------------------------------
__device__ __forceinline__ uint32_t smem_u32(const void* p) {
    uint32_t a;
    asm("{ .reg .u64 t; cvta.to.shared.u64 t, %1; cvt.u32.u64 %0, t; }" : "=r"(a) : "l"(p));
    return a;
}

__device__ __forceinline__ void ldsm_x4(uint32_t& r0, uint32_t& r1, uint32_t& r2, uint32_t& r3,
                                        uint32_t addr) {
    asm volatile("ldmatrix.sync.aligned.m8n8.x4.shared.b16 {%0,%1,%2,%3}, [%4];"
        : "=r"(r0), "=r"(r1), "=r"(r2), "=r"(r3) : "r"(addr));
}

__device__ __forceinline__ void mma_bf16(float* c, uint32_t a0, uint32_t a1, uint32_t a2, uint32_t a3,
                                         uint32_t b0, uint32_t b1) {
    asm volatile(
        "mma.sync.aligned.m16n8k16.row.col.f32.bf16.bf16.f32 "
        "{%0,%1,%2,%3}, {%4,%5,%6,%7}, {%8,%9}, {%0,%1,%2,%3};"
        : "+f"(c[0]), "+f"(c[1]), "+f"(c[2]), "+f"(c[3])
        : "r"(a0), "r"(a1), "r"(a2), "r"(a3), "r"(b0), "r"(b1));
}

__device__ __forceinline__ uint2 split_pack_hi(float4 v, float4& rem) {
    __nv_bfloat16 h0 = __float2bfloat16_rn(v.x), h1 = __float2bfloat16_rn(v.y);
    __nv_bfloat16 h2 = __float2bfloat16_rn(v.z), h3 = __float2bfloat16_rn(v.w);
    rem.x = v.x - __bfloat162float(h0);
    rem.y = v.y - __bfloat162float(h1);
    rem.z = v.z - __bfloat162float(h2);
    rem.w = v.w - __bfloat162float(h3);
    uint2 p;
    p.x = (uint32_t)__bfloat16_as_ushort(h0) | ((uint32_t)__bfloat16_as_ushort(h1) << 16);
    p.y = (uint32_t)__bfloat16_as_ushort(h2) | ((uint32_t)__bfloat16_as_ushort(h3) << 16);
    return p;
}
__device__ __forceinline__ uint2 pack_lo(float4 rem) {
    __nv_bfloat16 l0 = __float2bfloat16_rn(rem.x), l1 = __float2bfloat16_rn(rem.y);
    __nv_bfloat16 l2 = __float2bfloat16_rn(rem.z), l3 = __float2bfloat16_rn(rem.w);
    uint2 p;
    p.x = (uint32_t)__bfloat16_as_ushort(l0) | ((uint32_t)__bfloat16_as_ushort(l1) << 16);
    p.y = (uint32_t)__bfloat16_as_ushort(l2) | ((uint32_t)__bfloat16_as_ushort(l3) << 16);
    return p;
}
__device__ __forceinline__ void split2(float a, float b, uint32_t& ph, uint32_t& pl) {
    __nv_bfloat16 h0 = __float2bfloat16_rn(a), h1 = __float2bfloat16_rn(b);
    float ra = a - __bfloat162float(h0), rb = b - __bfloat162float(h1);
    __nv_bfloat16 l0 = __float2bfloat16_rn(ra), l1 = __float2bfloat16_rn(rb);
    ph = (uint32_t)__bfloat16_as_ushort(h0) | ((uint32_t)__bfloat16_as_ushort(h1) << 16);
    pl = (uint32_t)__bfloat16_as_ushort(l0) | ((uint32_t)__bfloat16_as_ushort(l1) << 16);
}

#define RSTRIDE 80
#define MAT_BYTES (128 * RSTRIDE)            // 10240
#define STAGE_BYTES (4 * MAT_BYTES)          // 40960
#define GEMM_SMEM (2 * STAGE_BYTES)          // 81920

// ---------------------------------------------------------------------------
// Kernel 0: weight preconversion (w1 and 3 projection weights -> bf16 hi/lo)
// ---------------------------------------------------------------------------
__global__ __launch_bounds__(256)
void prep_kernel(const float* __restrict__ w1, const float* __restrict__ wf,
                 const float* __restrict__ ws, const float* __restrict__ wg)
{
    const int idx = blockIdx.x * 256 + threadIdx.x;
    const int NW1 = ICH * KCONV;
    if (idx < NW1) {
        float v = w1[idx];
        __nv_bfloat16 h = __float2bfloat16_rn(v);
        g_w1h[idx] = h;
        g_w1l[idx] = __float2bfloat16_rn(v - __bfloat162float(h));
    } else {
        int j = idx - NW1;
        if (j >= 3 * NFC * ICH) return;
        const int which = j >> 15;      // 32768 per weight
        const int e = j & 32767;
        float v = (which == 0 ? wf : which == 1 ? ws : wg)[e];
        __nv_bfloat16 h = __float2bfloat16_rn(v);
        __nv_bfloat16 l = __float2bfloat16_rn(v - __bfloat162float(h));
        if (which == 0)      { g_wfh[e] = h; g_wfl[e] = l; }
        else if (which == 1) { g_wsh[e] = h; g_wsl[e] = l; }
        else                 { g_wgh[e] = h; g_wgl[e] = l; }
    }
}

// ---------------------------------------------------------------------------
// Kernel 1: conv1 implicit GEMM (M=8192, N=256, K=4096), mma.sync bf16 split
//   A converted inline from x (fp32); B loaded preconverted.
//   Epilogue: BN+ReLU, store y as bf16 hi/lo.
// ---------------------------------------------------------------------------
__global__ __launch_bounds__(256, 1)
void conv1_mma_kernel(const float* __restrict__ x,
                      const float* __restrict__ bnS,
                      const float* __restrict__ bnB)
{
    extern __shared__ char smem[];
    const uint32_t sbase = smem_u32(smem);

    const int tid = threadIdx.x;
    const int wid = tid >> 5;
    const int l   = tid & 31;
    const int warp_m = wid & 3;
    const int warp_n = wid >> 2;
    const int m0 = blockIdx.x * 128;
    const int n0 = blockIdx.y * 128;

    const int lr = tid >> 1;
    const int lq2 = (tid & 1) * 2;

    float acc[2][8][4];
    #pragma unroll
    for (int i = 0; i < 2; i++)
        #pragma unroll
        for (int j = 0; j < 8; j++)
            #pragma unroll
            for (int k = 0; k < 4; k++) acc[i][j][k] = 0.0f;

    float4 apf[4];
    uint4 bh2[2], bl2[2];

    auto gload = [&](int kt) {
        const int kb = kt * 32;
        #pragma unroll
        for (int j = 0; j < 4; j++) {
            const int q = lq2 + (j & 1) + ((j >> 1) << 2);
            const int k = kb + q * 4;
            const int rowA = m0 + lr;
            const int b  = rowA >> 10, oh = (rowA >> 5) & 31, ow = rowA & 31;
            const int ic = k >> 6, kh = (k >> 3) & 7, kw = k & 7;
            apf[j] = *(const float4*)&x[((size_t)(b * 64 + ic) * 256 + (oh * 8 + kh)) * 256 + (ow * 8 + kw)];
        }
        #pragma unroll
        for (int j = 0; j < 2; j++) {
            const int q4 = (tid & 1) * 2 + j;
            const int k = kb + q4 * 8;
            bh2[j] = *(const uint4*)&g_w1h[(size_t)(n0 + lr) * KCONV + k];
            bl2[j] = *(const uint4*)&g_w1l[(size_t)(n0 + lr) * KCONV + k];
        }
    };

    auto sstore = [&](int stage) {
        char* sb = smem + stage * STAGE_BYTES;
        #pragma unroll
        for (int j = 0; j < 4; j++) {
            const int q = lq2 + (j & 1) + ((j >> 1) << 2);
            const uint32_t off = (uint32_t)(lr * RSTRIDE + q * 8);
            float4 rem;
            uint2 ph = split_pack_hi(apf[j], rem);
            *(uint2*)(sb + off) = ph;
            *(uint2*)(sb + MAT_BYTES + off) = pack_lo(rem);
        }
        #pragma unroll
        for (int j = 0; j < 2; j++) {
            const int q4 = (tid & 1) * 2 + j;
            const uint32_t off4 = (uint32_t)(lr * RSTRIDE + q4 * 16);
            *(uint4*)(sb + 2 * MAT_BYTES + off4) = bh2[j];
            *(uint4*)(sb + 3 * MAT_BYTES + off4) = bl2[j];
        }
    };

    const uint32_t a_row = (uint32_t)(warp_m * 32 + (l & 15));
    const uint32_t a_coff = (uint32_t)((l >> 4) << 4);
    const uint32_t b_row = (uint32_t)(warp_n * 64 + (l & 7) + ((l >> 4) & 1) * 8);
    const uint32_t b_coff = (uint32_t)(((l >> 3) & 1) << 4);

    gload(0);
    sstore(0);
    __syncthreads();

    const int KT = KCONV / 32;
    for (int kt = 0; kt < KT; ++kt) {
        if (kt < KT - 1) gload(kt + 1);

        const uint32_t st = sbase + (uint32_t)((kt & 1) * STAGE_BYTES);
        #pragma unroll
        for (int ks = 0; ks < 2; ++ks) {
            uint32_t ah[2][4], al[2][4];
            #pragma unroll
            for (int bm = 0; bm < 2; ++bm) {
                const uint32_t aaddr = st + (a_row + bm * 16) * RSTRIDE + ks * 32 + a_coff;
                ldsm_x4(ah[bm][0], ah[bm][1], ah[bm][2], ah[bm][3], aaddr);
                ldsm_x4(al[bm][0], al[bm][1], al[bm][2], al[bm][3], aaddr + MAT_BYTES);
            }
            #pragma unroll
            for (int np = 0; np < 4; ++np) {
                uint32_t bh[4], bl[4];
                const uint32_t baddr = st + 2 * MAT_BYTES + (b_row + np * 16) * RSTRIDE + ks * 32 + b_coff;
                ldsm_x4(bh[0], bh[1], bh[2], bh[3], baddr);
                ldsm_x4(bl[0], bl[1], bl[2], bl[3], baddr + MAT_BYTES);
                #pragma unroll
                for (int bm = 0; bm < 2; ++bm) {
                    mma_bf16(acc[bm][np * 2],     ah[bm][0], ah[bm][1], ah[bm][2], ah[bm][3], bh[0], bh[1]);
                    mma_bf16(acc[bm][np * 2],     al[bm][0], al[bm][1], al[bm][2], al[bm][3], bh[0], bh[1]);
                    mma_bf16(acc[bm][np * 2],     ah[bm][0], ah[bm][1], ah[bm][2], ah[bm][3], bl[0], bl[1]);
                    mma_bf16(acc[bm][np * 2 + 1], ah[bm][0], ah[bm][1], ah[bm][2], ah[bm][3], bh[2], bh[3]);
                    mma_bf16(acc[bm][np * 2 + 1], al[bm][0], al[bm][1], al[bm][2], al[bm][3], bh[2], bh[3]);
                    mma_bf16(acc[bm][np * 2 + 1], ah[bm][0], ah[bm][1], ah[bm][2], ah[bm][3], bl[2], bl[3]);
                }
            }
        }

        if (kt < KT - 1) sstore((kt + 1) & 1);
        __syncthreads();
    }

    // epilogue: BN + ReLU, split-store y
    const int erow0 = m0 + warp_m * 32 + (l >> 2);
    const int ecol0 = n0 + warp_n * 64 + (l & 3) * 2;
    #pragma unroll
    for (int bm = 0; bm < 2; ++bm) {
        #pragma unroll
        for (int nb = 0; nb < 8; ++nb) {
            const int col = ecol0 + nb * 8;
            const float s0 = bnS[col], s1 = bnS[col + 1];
            const float v0 = bnB[col], v1 = bnB[col + 1];
            const int r0 = erow0 + bm * 16;
            float a0 = fmaxf(acc[bm][nb][0] * s0 + v0, 0.0f);
            float a1 = fmaxf(acc[bm][nb][1] * s1 + v1, 0.0f);
            float a2 = fmaxf(acc[bm][nb][2] * s0 + v0, 0.0f);
            float a3 = fmaxf(acc[bm][nb][3] * s1 + v1, 0.0f);
            uint32_t ph, pl;
            split2(a0, a1, ph, pl);
            *(uint32_t*)&g_yh[(size_t)r0 * ICH + col] = ph;
            *(uint32_t*)&g_yl[(size_t)r0 * ICH + col] = pl;
            split2(a2, a3, ph, pl);
            *(uint32_t*)&g_yh[(size_t)(r0 + 8) * ICH + col] = ph;
            *(uint32_t*)&g_yl[(size_t)(r0 + 8) * ICH + col] = pl;
        }
    }
}

// ---------------------------------------------------------------------------
// Kernel 2: 1x1 projections via mma (M=8192, N=128, K=256); z = proj id.
//   fai/sit stored [b][n][c]; gama stored transposed [b][c][m].
// ---------------------------------------------------------------------------
__global__ __launch_bounds__(256, 1)
void proj_mma_kernel(const float* __restrict__ sf, const float* __restrict__ bf,
                     const float* __restrict__ ss, const float* __restrict__ bs,
                     const float* __restrict__ sg, const float* __restrict__ bg)
{
    extern __shared__ char smem[];
    const uint32_t sbase = smem_u32(smem);

    const int z = blockIdx.z;
    const __nv_bfloat16* Wh = (z == 0) ? g_wfh : (z == 1) ? g_wsh : g_wgh;
    const __nv_bfloat16* Wl = (z == 0) ? g_wfl : (z == 1) ? g_wsl : g_wgl;
    const float* Sv = (z == 0) ? sf : (z == 1) ? ss : sg;
    const float* Bv = (z == 0) ? bf : (z == 1) ? bs : bg;

    const int tid = threadIdx.x;
    const int wid = tid >> 5;
    const int l   = tid & 31;
    const int warp_m = wid & 3;
    const int warp_n = wid >> 2;
    const int m0 = blockIdx.x * 128;

    const int lr = tid >> 1;

    float acc[2][8][4];
    #pragma unroll
    for (int i = 0; i < 2; i++)
        #pragma unroll
        for (int j = 0; j < 8; j++)
            #pragma unroll
            for (int k = 0; k < 4; k++) acc[i][j][k] = 0.0f;

    uint4 ah2[2], al2[2], bh2[2], bl2[2];

    auto gload = [&](int kt) {
        const int kb = kt * 32;
        #pragma unroll
        for (int j = 0; j < 2; j++) {
            const int q4 = (tid & 1) * 2 + j;
            const int k = kb + q4 * 8;
            ah2[j] = *(const uint4*)&g_yh[(size_t)(m0 + lr) * ICH + k];
            al2[j] = *(const uint4*)&g_yl[(size_t)(m0 + lr) * ICH + k];
            bh2[j] = *(const uint4*)&Wh[(size_t)lr * ICH + k];
            bl2[j] = *(const uint4*)&Wl[(size_t)lr * ICH + k];
        }
    };
    auto sstore = [&](int stage) {
        char* sb = smem + stage * STAGE_BYTES;
        #pragma unroll
        for (int j = 0; j < 2; j++) {
            const int q4 = (tid & 1) * 2 + j;
            const uint32_t off4 = (uint32_t)(lr * RSTRIDE + q4 * 16);
            *(uint4*)(sb + off4) = ah2[j];
            *(uint4*)(sb + MAT_BYTES + off4) = al2[j];
            *(uint4*)(sb + 2 * MAT_BYTES + off4) = bh2[j];
            *(uint4*)(sb + 3 * MAT_BYTES + off4) = bl2[j];
        }
    };

    const uint32_t a_row = (uint32_t)(warp_m * 32 + (l & 15));
    const uint32_t a_coff = (uint32_t)((l >> 4) << 4);
    const uint32_t b_row = (uint32_t)(warp_n * 64 + (l & 7) + ((l >> 4) & 1) * 8);
    const uint32_t b_coff = (uint32_t)(((l >> 3) & 1) << 4);

    gload(0);
    sstore(0);
    __syncthreads();

    const int KT = ICH / 32;  // 8
    for (int kt = 0; kt < KT; ++kt) {
        if (kt < KT - 1) gload(kt + 1);
        const uint32_t st = sbase + (uint32_t)((kt & 1) * STAGE_BYTES);
        #pragma unroll
        for (int ks = 0; ks < 2; ++ks) {
            uint32_t ah[2][4], al[2][4];
            #pragma unroll
            for (int bm = 0; bm < 2; ++bm) {
                const uint32_t aaddr = st + (a_row + bm * 16) * RSTRIDE + ks * 32 + a_coff;
                ldsm_x4(ah[bm][0], ah[bm][1], ah[bm][2], ah[bm][3], aaddr);
                ldsm_x4(al[bm][0], al[bm][1], al[bm][2], al[bm][3], aaddr + MAT_BYTES);
            }
            #pragma unroll
            for (int np = 0; np < 4; ++np) {
                uint32_t bh[4], bl[4];
                const uint32_t baddr = st + 2 * MAT_BYTES + (b_row + np * 16) * RSTRIDE + ks * 32 + b_coff;
                ldsm_x4(bh[0], bh[1], bh[2], bh[3], baddr);
                ldsm_x4(bl[0], bl[1], bl[2], bl[3], baddr + MAT_BYTES);
                #pragma unroll
                for (int bm = 0; bm < 2; ++bm) {
                    mma_bf16(acc[bm][np * 2],     ah[bm][0], ah[bm][1], ah[bm][2], ah[bm][3], bh[0], bh[1]);
                    mma_bf16(acc[bm][np * 2],     al[bm][0], al[bm][1], al[bm][2], al[bm][3], bh[0], bh[1]);
                    mma_bf16(acc[bm][np * 2],     ah[bm][0], ah[bm][1], ah[bm][2], ah[bm][3], bl[0], bl[1]);
                    mma_bf16(acc[bm][np * 2 + 1], ah[bm][0], ah[bm][1], ah[bm][2], ah[bm][3], bh[2], bh[3]);
                    mma_bf16(acc[bm][np * 2 + 1], al[bm][0], al[bm][1], al[bm][2], al[bm][3], bh[2], bh[3]);
                    mma_bf16(acc[bm][np * 2 + 1], ah[bm][0], ah[bm][1], ah[bm][2], ah[bm][3], bl[2], bl[3]);
                }
            }
        }
        if (kt < KT - 1) sstore((kt + 1) & 1);
        __syncthreads();
    }

    // epilogue: BN + ReLU + split-store
    const int erow0 = m0 + warp_m * 32 + (l >> 2);
    const int ecol0 = warp_n * 64 + (l & 3) * 2;
    #pragma unroll
    for (int bm = 0; bm < 2; ++bm) {
        #pragma unroll
        for (int nb = 0; nb < 8; ++nb) {
            const int col = ecol0 + nb * 8;
            const float s0 = Sv[col], s1 = Sv[col + 1];
            const float v0 = Bv[col], v1 = Bv[col + 1];
            const int r0 = erow0 + bm * 16;
            float a0 = fmaxf(acc[bm][nb][0] * s0 + v0, 0.0f);
            float a1 = fmaxf(acc[bm][nb][1] * s1 + v1, 0.0f);
            float a2 = fmaxf(acc[bm][nb][2] * s0 + v0, 0.0f);
            float a3 = fmaxf(acc[bm][nb][3] * s1 + v1, 0.0f);
            if (z < 2) {
                __nv_bfloat16* Oh = (z == 0) ? g_faih : g_sith;
                __nv_bfloat16* Ol = (z == 0) ? g_fail_ : g_sitl;
                uint32_t ph, pl;
                split2(a0, a1, ph, pl);
                *(uint32_t*)&Oh[(size_t)r0 * NFC + col] = ph;
                *(uint32_t*)&Ol[(size_t)r0 * NFC + col] = pl;
                split2(a2, a3, ph, pl);
                *(uint32_t*)&Oh[(size_t)(r0 + 8) * NFC + col] = ph;
                *(uint32_t*)&Ol[(size_t)(r0 + 8) * NFC + col] = pl;
            } else {
                // gama transposed: [b][c][m]
                const int bb = r0 >> 10;
                const int n  = r0 & 1023;
                const size_t base = (size_t)bb * NFC * NPIX;
                float vals[4] = {a0, a1, a2, a3};
                const int cols[2] = {col, col + 1};
                const int rows[2] = {n, n + 8};
                #pragma unroll
                for (int ii = 0; ii < 4; ii++) {
                    const int cc = cols[ii & 1];
                    const int rr = rows[ii >> 1];
                    __nv_bfloat16 h = __float2bfloat16_rn(vals[ii]);
                    g_gTh[base + (size_t)cc * NPIX + rr] = h;
                    g_gTl[base + (size_t)cc * NPIX + rr] =
                        __float2bfloat16_rn(vals[ii] - __bfloat162float(h));
                }
            }
        }
    }
}

// ---------------------------------------------------------------------------
// Kernel 3: score S = sigmoid(fai . sit) via mma (per batch: M=N=1024, K=128)
// ---------------------------------------------------------------------------
__global__ __launch_bounds__(256, 1)
void score_mma_kernel()
{
    extern __shared__ char smem[];
    const uint32_t sbase = smem_u32(smem);

    const int b  = blockIdx.z;
    const int m0 = blockIdx.x * 128;
    const int n0 = blockIdx.y * 128;
    const int tid = threadIdx.x;
    const int wid = tid >> 5;
    const int l   = tid & 31;
    const int warp_m = wid & 3;
    const int warp_n = wid >> 2;
    const int lr = tid >> 1;

    const size_t abase = (size_t)b * NPIX * NFC;

    float acc[2][8][4];
    #pragma unroll
    for (int i = 0; i < 2; i++)
        #pragma unroll
        for (int j = 0; j < 8; j++)
            #pragma unroll
            for (int k = 0; k < 4; k++) acc[i][j][k] = 0.0f;

    uint4 ah2[2], al2[2], bh2[2], bl2[2];

    auto gload = [&](int kt) {
        const int kb = kt * 32;
        #pragma unroll
        for (int j = 0; j < 2; j++) {
            const int q4 = (tid & 1) * 2 + j;
            const int k = kb + q4 * 8;
            ah2[j] = *(const uint4*)&g_faih[abase + (size_t)(m0 + lr) * NFC + k];
            al2[j] = *(const uint4*)&g_fail_[abase + (size_t)(m0 + lr) * NFC + k];
            bh2[j] = *(const uint4*)&g_sith[abase + (size_t)(n0 + lr) * NFC + k];
            bl2[j] = *(const uint4*)&g_sitl[abase + (size_t)(n0 + lr) * NFC + k];
        }
    };
    auto sstore = [&](int stage) {
        char* sb = smem + stage * STAGE_BYTES;
        #pragma unroll
        for (int j = 0; j < 2; j++) {
            const int q4 = (tid & 1) * 2 + j;
            const uint32_t off4 = (uint32_t)(lr * RSTRIDE + q4 * 16);
            *(uint4*)(sb + off4) = ah2[j];
            *(uint4*)(sb + MAT_BYTES + off4) = al2[j];
            *(uint4*)(sb + 2 * MAT_BYTES + off4) = bh2[j];
            *(uint4*)(sb + 3 * MAT_BYTES + off4) = bl2[j];
        }
    };

    const uint32_t a_row = (uint32_t)(warp_m * 32 + (l & 15));
    const uint32_t a_coff = (uint32_t)((l >> 4) << 4);
    const uint32_t b_row = (uint32_t)(warp_n * 64 + (l & 7) + ((l >> 4) & 1) * 8);
    const uint32_t b_coff = (uint32_t)(((l >> 3) & 1) << 4);

    gload(0);
    sstore(0);
    __syncthreads();

    const int KT = NFC / 32;  // 4
    for (int kt = 0; kt < KT; ++kt) {
        if (kt < KT - 1) gload(kt + 1);
        const uint32_t st = sbase + (uint32_t)((kt & 1) * STAGE_BYTES);
        #pragma unroll
        for (int ks = 0; ks < 2; ++ks) {
            uint32_t ah[2][4], al[2][4];
            #pragma unroll
            for (int bm = 0; bm < 2; ++bm) {
                const uint32_t aaddr = st + (a_row + bm * 16) * RSTRIDE + ks * 32 + a_coff;
                ldsm_x4(ah[bm][0], ah[bm][1], ah[bm][2], ah[bm][3], aaddr);
                ldsm_x4(al[bm][0], al[bm][1], al[bm][2], al[bm][3], aaddr + MAT_BYTES);
            }
            #pragma unroll
            for (int np = 0; np < 4; ++np) {
                uint32_t bh[4], bl[4];
                const uint32_t baddr = st + 2 * MAT_BYTES + (b_row + np * 16) * RSTRIDE + ks * 32 + b_coff;
                ldsm_x4(bh[0], bh[1], bh[2], bh[3], baddr);
                ldsm_x4(bl[0], bl[1], bl[2], bl[3], baddr + MAT_BYTES);
                #pragma unroll
                for (int bm = 0; bm < 2; ++bm) {
                    mma_bf16(acc[bm][np * 2],     ah[bm][0], ah[bm][1], ah[bm][2], ah[bm][3], bh[0], bh[1]);
                    mma_bf16(acc[bm][np * 2],     al[bm][0], al[bm][1], al[bm][2], al[bm][3], bh[0], bh[1]);
                    mma_bf16(acc[bm][np * 2],     ah[bm][0], ah[bm][1], ah[bm][2], ah[bm][3], bl[0], bl[1]);
                    mma_bf16(acc[bm][np * 2 + 1], ah[bm][0], ah[bm][1], ah[bm][2], ah[bm][3], bh[2], bh[3]);
                    mma_bf16(acc[bm][np * 2 + 1], al[bm][0], al[bm][1], al[bm][2], al[bm][3], bh[2], bh[3]);
                    mma_bf16(acc[bm][np * 2 + 1], ah[bm][0], ah[bm][1], ah[bm][2], ah[bm][3], bl[2], bl[3]);
                }
            }
        }
        if (kt < KT - 1) sstore((kt + 1) & 1);
        __syncthreads();
    }

    // epilogue: sigmoid + split-store S
    const size_t sb_out = (size_t)b * NPIX * NPIX;
    const int erow0 = m0 + warp_m * 32 + (l >> 2);
    const int ecol0 = n0 + warp_n * 64 + (l & 3) * 2;
    #pragma unroll
    for (int bm = 0; bm < 2; ++bm) {
        #pragma unroll
        for (int nb = 0; nb < 8; ++nb) {
            const int col = ecol0 + nb * 8;
            const int r0 = erow0 + bm * 16;
            float a0 = 1.0f / (1.0f + expf(-acc[bm][nb][0]));
            float a1 = 1.0f / (1.0f + expf(-acc[bm][nb][1]));
            float a2 = 1.0f / (1.0f + expf(-acc[bm][nb][2]));
            float a3 = 1.0f / (1.0f + expf(-acc[bm][nb][3]));
            uint32_t ph, pl;
            split2(a0, a1, ph, pl);
            *(uint32_t*)&g_Sh[sb_out + (size_t)r0 * NPIX + col] = ph;
            *(uint32_t*)&g_Sl[sb_out + (size_t)r0 * NPIX + col] = pl;
            split2(a2, a3, ph, pl);
            *(uint32_t*)&g_Sh[sb_out + (size_t)(r0 + 8) * NPIX + col] = ph;
            *(uint32_t*)&g_Sl[sb_out + (size_t)(r0 + 8) * NPIX + col] = pl;
        }
    }
}

// ---------------------------------------------------------------------------
// Kernel 4: att[n][c] = sum_m S[n][m] gamaT[c][m]  via mma
//   per batch: M=1024 (tile 64), N=128, K=1024.  grid (16,1,8)
// ---------------------------------------------------------------------------
#define AT_A_HI 0
#define AT_A_LO 5120
#define AT_B_HI 10240
#define AT_B_LO 20480
#define AT_STAGE 30720
#define AT_SMEM (2 * AT_STAGE)

__global__ __launch_bounds__(256, 1)
void attn_mma_kernel()
{
    extern __shared__ char smem[];
    const uint32_t sbase = smem_u32(smem);

    const int b  = blockIdx.z;
    const int m0 = blockIdx.x * 64;
    const int tid = threadIdx.x;
    const int wid = tid >> 5;
    const int l   = tid & 31;
    const int warp_m = wid & 1;        // 2 warps in M (32 rows)
    const int warp_n = wid >> 1;       // 4 warps in N (32 cols)

    const size_t sBase = (size_t)b * NPIX * NPIX;
    const size_t gBase = (size_t)b * NFC * NPIX;

    float acc[2][4][4];
    #pragma unroll
    for (int i = 0; i < 2; i++)
        #pragma unroll
        for (int j = 0; j < 4; j++)
            #pragma unroll
            for (int k = 0; k < 4; k++) acc[i][j][k] = 0.0f;

    uint4 ah1, al1, bh2[2], bl2[2];
    const int ar = tid >> 2;            // A row 0..63
    const int aq = tid & 3;             // A chunk 0..3
    const int br = tid >> 1;            // B row 0..127

    auto gload = [&](int kt) {
        const int kb = kt * 32;
        {
            const int k = kb + aq * 8;
            ah1 = *(const uint4*)&g_Sh[sBase + (size_t)(m0 + ar) * NPIX + k];
            al1 = *(const uint4*)&g_Sl[sBase + (size_t)(m0 + ar) * NPIX + k];
        }
        #pragma unroll
        for (int j = 0; j < 2; j++) {
            const int q4 = (tid & 1) * 2 + j;
            const int k = kb + q4 * 8;
            bh2[j] = *(const uint4*)&g_gTh[gBase + (size_t)br * NPIX + k];
            bl2[j] = *(const uint4*)&g_gTl[gBase + (size_t)br * NPIX + k];
        }
    };
    auto sstore = [&](int stage) {
        char* sb = smem + stage * AT_STAGE;
        {
            const uint32_t off = (uint32_t)(ar * RSTRIDE + aq * 16);
            *(uint4*)(sb + AT_A_HI + off) = ah1;
            *(uint4*)(sb + AT_A_LO + off) = al1;
        }
        #pragma unroll
        for (int j = 0; j < 2; j++) {
            const int q4 = (tid & 1) * 2 + j;
            const uint32_t off = (uint32_t)(br * RSTRIDE + q4 * 16);
            *(uint4*)(sb + AT_B_HI + off) = bh2[j];
            *(uint4*)(sb + AT_B_LO + off) = bl2[j];
        }
    };

    const uint32_t a_row = (uint32_t)(warp_m * 32 + (l & 15));
    const uint32_t a_coff = (uint32_t)((l >> 4) << 4);
    const uint32_t b_row = (uint32_t)(warp_n * 32 + (l & 7) + ((l >> 4) & 1) * 8);
    const uint32_t b_coff = (uint32_t)(((l >> 3) & 1) << 4);

    gload(0);
    sstore(0);
    __syncthreads();

    const int KT = NPIX / 32;   // 32
    for (int kt = 0; kt < KT; ++kt) {
        if (kt < KT - 1) gload(kt + 1);
        const uint32_t st = sbase + (uint32_t)((kt & 1) * AT_STAGE);
        #pragma unroll
        for (int ks = 0; ks < 2; ++ks) {
            uint32_t ah[2][4], al[2][4];
            #pragma unroll
            for (int bm = 0; bm < 2; ++bm) {
                const uint32_t aaddr = st + AT_A_HI + (a_row + bm * 16) * RSTRIDE + ks * 32 + a_coff;
                ldsm_x4(ah[bm][0], ah[bm][1], ah[bm][2], ah[bm][3], aaddr);
                ldsm_x4(al[bm][0], al[bm][1], al[bm][2], al[bm][3], aaddr + (AT_A_LO - AT_A_HI));
            }
            #pragma unroll
            for (int np = 0; np < 2; ++np) {
                uint32_t bh[4], bl[4];
                const uint32_t baddr = st + AT_B_HI + (b_row + np * 16) * RSTRIDE + ks * 32 + b_coff;
                ldsm_x4(bh[0], bh[1], bh[2], bh[3], baddr);
                ldsm_x4(bl[0], bl[1], bl[2], bl[3], baddr + (AT_B_LO - AT_B_HI));
                #pragma unroll
                for (int bm = 0; bm < 2; ++bm) {
                    mma_bf16(acc[bm][np * 2],     ah[bm][0], ah[bm][1], ah[bm][2], ah[bm][3], bh[0], bh[1]);
                    mma_bf16(acc[bm][np * 2],     al[bm][0], al[bm][1], al[bm][2], al[bm][3], bh[0], bh[1]);
                    mma_bf16(acc[bm][np * 2],     ah[bm][0], ah[bm][1], ah[bm][2], ah[bm][3], bl[0], bl[1]);
                    mma_bf16(acc[bm][np * 2 + 1], ah[bm][0], ah[bm][1], ah[bm][2], ah[bm][3], bh[2], bh[3]);
                    mma_bf16(acc[bm][np * 2 + 1], al[bm][0], al[bm][1], al[bm][2], al[bm][3], bh[2], bh[3]);
                    mma_bf16(acc[bm][np * 2 + 1], ah[bm][0], ah[bm][1], ah[bm][2], ah[bm][3], bl[2], bl[3]);
                }
            }
        }
        if (kt < KT - 1) sstore((kt + 1) & 1);
        __syncthreads();
    }

    // epilogue: fp32 store to g_att
    const int erow0 = m0 + warp_m * 32 + (l >> 2);
    const int ecol0 = warp_n * 32 + (l & 3) * 2;
    #pragma unroll
    for (int bm = 0; bm < 2; ++bm) {
        #pragma unroll
        for (int nb = 0; nb < 4; ++nb) {
            const int col = ecol0 + nb * 8;
            const int r0 = erow0 + bm * 16;
            float2 o0 = {acc[bm][nb][0], acc[bm][nb][1]};
            float2 o1 = {acc[bm][nb][2], acc[bm][nb][3]};
            *(float2*)&g_att[((size_t)b * NPIX + r0) * NFC + col] = o0;
            *(float2*)&g_att[((size_t)b * NPIX + r0 + 8) * NFC + col] = o1;
        }
    }
}

// ---------------------------------------------------------------------------
// Kernel 5: bilinear upsample x8, align_corners=True
// ---------------------------------------------------------------------------
__global__ __launch_bounds__(256)
void upsample_kernel(float* __restrict__ out)
{
    const long long idx = (long long)blockIdx.x * blockDim.x + threadIdx.x;
    const int xo = (int)(idx & 255);
    const int yo = (int)((idx >> 8) & 255);
    const int c  = (int)((idx >> 16) & 127);
    const int b  = (int)(idx >> 23);

    const float sc = (float)(31.0 / 255.0);
    const float ysf = (float)yo * sc;
    const float xsf = (float)xo * sc;
    int y0 = (int)floorf(ysf);
    int x0 = (int)floorf(xsf);
    const float wy = ysf - (float)y0;
    const float wx = xsf - (float)x0;
    const int y1 = min(y0 + 1, 31);
    const int x1 = min(x0 + 1, 31);

    const float* base = g_att + (size_t)b * NPIX * NFC;
    const float v00 = base[(size_t)(y0 * 32 + x0) * NFC + c];
    const float v10 = base[(size_t)(y1 * 32 + x0) * NFC + c];
    const float v01 = base[(size_t)(y0 * 32 + x1) * NFC + c];
    const float v11 = base[(size_t)(y1 * 32 + x1) * NFC + c];

    const float top0 = v00 * (1.0f - wy) + v10 * wy;
    const float top1 = v01 * (1.0f - wy) + v11 * wy;
    out[idx] = top0 * (1.0f - wx) + top1 * wx;
}

// ---------------------------------------------------------------------------
// Launch
// ---------------------------------------------------------------------------
extern "C" void kernel_launch(void* const* d_in, const int* in_sizes, int n_in,
                              void* d_out, int out_size)
{
    const float* x     = (const float*)d_in[0];
    const float* w1    = (const float*)d_in[1];
    const float* bn1_s = (const float*)d_in[2];
    const float* bn1_b = (const float*)d_in[3];
    const float* w_fai = (const float*)d_in[4];
    const float* bnf_s = (const float*)d_in[5];
    const float* bnf_b = (const float*)d_in[6];
    const float* w_sit = (const float*)d_in[7];
    const float* bns_s = (const float*)d_in[8];
    const float* bns_b = (const float*)d_in[9];
    const float* w_gam = (const float*)d_in[10];
    const float* bng_s = (const float*)d_in[11];
    const float* bng_b = (const float*)d_in[12];
    float* out = (float*)d_out;

    static bool attr_done = false;
    if (!attr_done) {
        cudaFuncSetAttribute(conv1_mma_kernel, cudaFuncAttributeMaxDynamicSharedMemorySize, GEMM_SMEM);
        cudaFuncSetAttribute(proj_mma_kernel,  cudaFuncAttributeMaxDynamicSharedMemorySize, GEMM_SMEM);
        cudaFuncSetAttribute(score_mma_kernel, cudaFuncAttributeMaxDynamicSharedMemorySize, GEMM_SMEM);
        cudaFuncSetAttribute(attn_mma_kernel,  cudaFuncAttributeMaxDynamicSharedMemorySize, AT_SMEM);
        attr_done = true;
    }

    // 0. weight preconversion
    {
        const int total = ICH * KCONV + 3 * NFC * ICH;
        prep_kernel<<<(total + 255) / 256, 256>>>(w1, w_fai, w_sit, w_gam);
    }
    // 1. conv1 + BN + ReLU -> y (bf16 hi/lo)
    {
        dim3 grid(MROWS / 128, ICH / 128);
        conv1_mma_kernel<<<grid, 256, GEMM_SMEM>>>(x, bn1_s, bn1_b);
    }
    // 2. projections -> fai/sit (bf16 hi/lo), gamaT (bf16 hi/lo)
    {
        dim3 grid(MROWS / 128, 1, 3);
        proj_mma_kernel<<<grid, 256, GEMM_SMEM>>>(bnf_s, bnf_b, bns_s, bns_b, bng_s, bng_b);
    }
    // 3. S = sigmoid(fai . sit) (bf16 hi/lo)
    {
        dim3 grid(NPIX / 128, NPIX / 128, BATCH);
        score_mma_kernel<<<grid, 256, GEMM_SMEM>>>();
    }
    // 4. att = S @ gamaT
    {
        dim3 grid(NPIX / 64, 1, BATCH);
        attn_mma_kernel<<<grid, 256, AT_SMEM>>>();
    }
    // 5. bilinear upsample x8
    {
        const long long total = (long long)BATCH * NFC * 256 * 256;
        upsample_kernel<<<(unsigned)(total / 256), 256>>>(out);
    }
}

// round 5
// speedup vs baseline: 2.3622x; 1.1340x over previous
#include <cuda_runtime.h>
#include <cuda_bf16.h>
#include <math.h>
#include <stdint.h>

// ---------------------------------------------------------------------------
// Problem constants
// ---------------------------------------------------------------------------
#define BATCH 8
#define ICH   256
#define NFC   128
#define NPIX  1024
#define KCONV 4096
#define MROWS 8192

// ---------------------------------------------------------------------------
// Device scratch (bf16 hi/lo split pairs throughout the GEMM chain)
// ---------------------------------------------------------------------------
__device__ __nv_bfloat16 g_w1h[ICH * KCONV], g_w1l[ICH * KCONV];
__device__ __nv_bfloat16 g_wfh[NFC * ICH],  g_wfl[NFC * ICH];
__device__ __nv_bfloat16 g_wsh[NFC * ICH],  g_wsl[NFC * ICH];
__device__ __nv_bfloat16 g_wgh[NFC * ICH],  g_wgl[NFC * ICH];

__device__ __nv_bfloat16 g_xh[MROWS * KCONV], g_xl[MROWS * KCONV];         // im2col(x) [row][4096]
__device__ __nv_bfloat16 g_yh[MROWS * ICH],  g_yl[MROWS * ICH];            // conv out [row][256]
__device__ __nv_bfloat16 g_faih[BATCH * NPIX * NFC], g_fail_[BATCH * NPIX * NFC];
__device__ __nv_bfloat16 g_sith[BATCH * NPIX * NFC], g_sitl[BATCH * NPIX * NFC];
__device__ __nv_bfloat16 g_gTh[BATCH * NFC * NPIX],  g_gTl[BATCH * NFC * NPIX];   // [b][c][m]
__device__ __nv_bfloat16 g_Sh[BATCH * NPIX * NPIX],  g_Sl[BATCH * NPIX * NPIX];   // [b][n][m]
__device__ float g_att[BATCH * NPIX * NFC];                                        // [b][n][128]

// ---------------------------------------------------------------------------
// Portable warp-MMA helpers (base sm_103, no 'a' features)
// ---------------------------------------------------------------------------
__device__ __forceinline__ uint32_t smem_u32(const void* p) {
    uint32_t a;
    asm("{ .reg .u64 t; cvta.to.shared.u64 t, %1; cvt.u32.u64 %0, t; }" : "=r"(a) : "l"(p));
    return a;
}

__device__ __forceinline__ void ldsm_x4(uint32_t& r0, uint32_t& r1, uint32_t& r2, uint32_t& r3,
                                        uint32_t addr) {
    asm volatile("ldmatrix.sync.aligned.m8n8.x4.shared.b16 {%0,%1,%2,%3}, [%4];"
        : "=r"(r0), "=r"(r1), "=r"(r2), "=r"(r3) : "r"(addr));
}

__device__ __forceinline__ void mma_bf16(float* c, const uint32_t* a,
                                         uint32_t b0, uint32_t b1) {
    asm volatile(
        "mma.sync.aligned.m16n8k16.row.col.f32.bf16.bf16.f32 "
        "{%0,%1,%2,%3}, {%4,%5,%6,%7}, {%8,%9}, {%0,%1,%2,%3};"
        : "+f"(c[0]), "+f"(c[1]), "+f"(c[2]), "+f"(c[3])
        : "r"(a[0]), "r"(a[1]), "r"(a[2]), "r"(a[3]), "r"(b0), "r"(b1));
}

__device__ __forceinline__ void split2(float a, float b, uint32_t& ph, uint32_t& pl) {
    __nv_bfloat16 h0 = __float2bfloat16_rn(a), h1 = __float2bfloat16_rn(b);
    float ra = a - __bfloat162float(h0), rb = b - __bfloat162float(h1);
    __nv_bfloat16 l0 = __float2bfloat16_rn(ra), l1 = __float2bfloat16_rn(rb);
    ph = (uint32_t)__bfloat16_as_ushort(h0) | ((uint32_t)__bfloat16_as_ushort(h1) << 16);
    pl = (uint32_t)__bfloat16_as_ushort(l0) | ((uint32_t)__bfloat16_as_ushort(l1) << 16);
}

#define RSTRIDE 80
#define MAT_BYTES (128 * RSTRIDE)            // 10240
#define STAGE_BYTES (4 * MAT_BYTES)          // 40960
#define GEMM_SMEM (2 * STAGE_BYTES)          // 81920

// ---------------------------------------------------------------------------
// Kernel 0a: weight preconversion
// ---------------------------------------------------------------------------
__global__ __launch_bounds__(256)
void prep_kernel(const float* __restrict__ w1, const float* __restrict__ wf,
                 const float* __restrict__ ws, const float* __restrict__ wg)
{
    const int idx = blockIdx.x * 256 + threadIdx.x;
    const int NW1 = ICH * KCONV;
    if (idx < NW1) {
        float v = w1[idx];
        __nv_bfloat16 h = __float2bfloat16_rn(v);
        g_w1h[idx] = h;
        g_w1l[idx] = __float2bfloat16_rn(v - __bfloat162float(h));
    } else {
        int j = idx - NW1;
        if (j >= 3 * NFC * ICH) return;
        const int which = j >> 15;
        const int e = j & 32767;
        float v = (which == 0 ? wf : which == 1 ? ws : wg)[e];
        __nv_bfloat16 h = __float2bfloat16_rn(v);
        __nv_bfloat16 l = __float2bfloat16_rn(v - __bfloat162float(h));
        if (which == 0)      { g_wfh[e] = h; g_wfl[e] = l; }
        else if (which == 1) { g_wsh[e] = h; g_wsl[e] = l; }
        else                 { g_wgh[e] = h; g_wgl[e] = l; }
    }
}

// ---------------------------------------------------------------------------
// Kernel 0b: im2col of x into bf16 hi/lo (stride-8 8x8 conv = pure permutation)
//   CTA = (b, oh, ic-chunk of 8). Reads coalesced, smem transpose, writes
//   coalesced. Output row = b*1024+oh*32+ow, col = ic*64 + kh*8 + kw.
// ---------------------------------------------------------------------------
#define I2C_RS 264                        // smem row stride (bf16 units)
#define I2C_SMEM (2 * 64 * I2C_RS * 2)    // 67584 bytes

__global__ __launch_bounds__(256, 1)
void im2col_kernel(const float* __restrict__ x)
{
    extern __shared__ char smraw[];
    __nv_bfloat16* sh = (__nv_bfloat16*)smraw;
    __nv_bfloat16* sl = (__nv_bfloat16*)(smraw + 64 * I2C_RS * 2);

    const int bx = blockIdx.x;
    const int icc = bx & 7;
    const int oh  = (bx >> 3) & 31;
    const int b   = bx >> 8;
    const int t = threadIdx.x;

    // load: 4096 float4 over 16 iterations, fully coalesced
    #pragma unroll
    for (int it = 0; it < 16; ++it) {
        const int f = t + it * 256;
        const int w4 = f & 63;
        const int kh = (f >> 6) & 7;
        const int i  = f >> 9;
        const float4 v = *(const float4*)&x[((size_t)(b * 64 + icc * 8 + i) * 256 + oh * 8 + kh) * 256 + w4 * 4];
        const int row = i * 8 + kh;
        __nv_bfloat16 h0 = __float2bfloat16_rn(v.x), h1 = __float2bfloat16_rn(v.y);
        __nv_bfloat16 h2 = __float2bfloat16_rn(v.z), h3 = __float2bfloat16_rn(v.w);
        sh[row * I2C_RS + w4 * 4 + 0] = h0;
        sh[row * I2C_RS + w4 * 4 + 1] = h1;
        sh[row * I2C_RS + w4 * 4 + 2] = h2;
        sh[row * I2C_RS + w4 * 4 + 3] = h3;
        sl[row * I2C_RS + w4 * 4 + 0] = __float2bfloat16_rn(v.x - __bfloat162float(h0));
        sl[row * I2C_RS + w4 * 4 + 1] = __float2bfloat16_rn(v.y - __bfloat162float(h1));
        sl[row * I2C_RS + w4 * 4 + 2] = __float2bfloat16_rn(v.z - __bfloat162float(h2));
        sl[row * I2C_RS + w4 * 4 + 3] = __float2bfloat16_rn(v.w - __bfloat162float(h3));
    }
    __syncthreads();

    // write: 2048 uint4 per matrix over 8 iterations, coalesced
    #pragma unroll
    for (int it = 0; it < 8; ++it) {
        const int f = t + it * 256;
        const int kh = f & 7;
        const int i  = (f >> 3) & 7;
        const int ow = f >> 6;
        const int row = i * 8 + kh;
        const size_t r = (size_t)b * 1024 + oh * 32 + ow;
        const size_t kbase = (size_t)(icc * 8 + i) * 64 + kh * 8;
        *(uint4*)&g_xh[r * KCONV + kbase] = *(const uint4*)&sh[row * I2C_RS + ow * 8];
        *(uint4*)&g_xl[r * KCONV + kbase] = *(const uint4*)&sl[row * I2C_RS + ow * 8];
    }
}

// ---------------------------------------------------------------------------
// Shared inner-loop macro: variant-major MMA issue (dependency distance 16)
//   acc[2][8][4], ah/al[2][4], bhf/blf[4][4]
// ---------------------------------------------------------------------------
#define MMA_BLOCK_128(acc, ah, al, bhf, blf)                                   \
    do {                                                                       \
        _Pragma("unroll")                                                      \
        for (int np = 0; np < 4; ++np) {                                       \
            _Pragma("unroll")                                                  \
            for (int bm = 0; bm < 2; ++bm) {                                   \
                mma_bf16(acc[bm][np * 2],     ah[bm], bhf[np][0], bhf[np][1]); \
                mma_bf16(acc[bm][np * 2 + 1], ah[bm], bhf[np][2], bhf[np][3]); \
            }                                                                  \
        }                                                                      \
        _Pragma("unroll")                                                      \
        for (int np = 0; np < 4; ++np) {                                       \
            _Pragma("unroll")                                                  \
            for (int bm = 0; bm < 2; ++bm) {                                   \
                mma_bf16(acc[bm][np * 2],     al[bm], bhf[np][0], bhf[np][1]); \
                mma_bf16(acc[bm][np * 2 + 1], al[bm], bhf[np][2], bhf[np][3]); \
            }                                                                  \
        }                                                                      \
        _Pragma("unroll")                                                      \
        for (int np = 0; np < 4; ++np) {                                       \
            _Pragma("unroll")                                                  \
            for (int bm = 0; bm < 2; ++bm) {                                   \
                mma_bf16(acc[bm][np * 2],     ah[bm], blf[np][0], blf[np][1]); \
                mma_bf16(acc[bm][np * 2 + 1], ah[bm], blf[np][2], blf[np][3]); \
            }                                                                  \
        }                                                                      \
    } while (0)

// ---------------------------------------------------------------------------
// Kernel 1: conv1 GEMM (M=8192, N=256, K=4096) — pure bf16 split GEMM
// ---------------------------------------------------------------------------
__global__ __launch_bounds__(256, 1)
void conv1_mma_kernel(const float* __restrict__ bnS, const float* __restrict__ bnB)
{
    extern __shared__ char smem[];
    const uint32_t sbase = smem_u32(smem);

    const int tid = threadIdx.x;
    const int wid = tid >> 5;
    const int l   = tid & 31;
    const int warp_m = wid & 3;
    const int warp_n = wid >> 2;
    const int m0 = blockIdx.x * 128;
    const int n0 = blockIdx.y * 128;
    const int lr = tid >> 1;

    float acc[2][8][4];
    #pragma unroll
    for (int i = 0; i < 2; i++)
        #pragma unroll
        for (int j = 0; j < 8; j++)
            #pragma unroll
            for (int k = 0; k < 4; k++) acc[i][j][k] = 0.0f;

    uint4 ah2[2], al2[2], bh2[2], bl2[2];

    auto gload = [&](int kt) {
        const int kb = kt * 32;
        #pragma unroll
        for (int j = 0; j < 2; j++) {
            const int q4 = (tid & 1) * 2 + j;
            const int k = kb + q4 * 8;
            ah2[j] = *(const uint4*)&g_xh[(size_t)(m0 + lr) * KCONV + k];
            al2[j] = *(const uint4*)&g_xl[(size_t)(m0 + lr) * KCONV + k];
            bh2[j] = *(const uint4*)&g_w1h[(size_t)(n0 + lr) * KCONV + k];
            bl2[j] = *(const uint4*)&g_w1l[(size_t)(n0 + lr) * KCONV + k];
        }
    };
    auto sstore = [&](int stage) {
        char* sb = smem + stage * STAGE_BYTES;
        #pragma unroll
        for (int j = 0; j < 2; j++) {
            const int q4 = (tid & 1) * 2 + j;
            const uint32_t off4 = (uint32_t)(lr * RSTRIDE + q4 * 16);
            *(uint4*)(sb + off4) = ah2[j];
            *(uint4*)(sb + MAT_BYTES + off4) = al2[j];
            *(uint4*)(sb + 2 * MAT_BYTES + off4) = bh2[j];
            *(uint4*)(sb + 3 * MAT_BYTES + off4) = bl2[j];
        }
    };

    const uint32_t a_row = (uint32_t)(warp_m * 32 + (l & 15));
    const uint32_t a_coff = (uint32_t)((l >> 4) << 4);
    const uint32_t b_row = (uint32_t)(warp_n * 64 + (l & 7) + ((l >> 4) & 1) * 8);
    const uint32_t b_coff = (uint32_t)(((l >> 3) & 1) << 4);

    gload(0);
    sstore(0);
    __syncthreads();

    const int KT = KCONV / 32;
    for (int kt = 0; kt < KT; ++kt) {
        if (kt < KT - 1) gload(kt + 1);
        const uint32_t st = sbase + (uint32_t)((kt & 1) * STAGE_BYTES);
        #pragma unroll
        for (int ks = 0; ks < 2; ++ks) {
            uint32_t ah[2][4], al[2][4], bhf[4][4], blf[4][4];
            #pragma unroll
            for (int bm = 0; bm < 2; ++bm) {
                const uint32_t aaddr = st + (a_row + bm * 16) * RSTRIDE + ks * 32 + a_coff;
                ldsm_x4(ah[bm][0], ah[bm][1], ah[bm][2], ah[bm][3], aaddr);
                ldsm_x4(al[bm][0], al[bm][1], al[bm][2], al[bm][3], aaddr + MAT_BYTES);
            }
            #pragma unroll
            for (int np = 0; np < 4; ++np) {
                const uint32_t baddr = st + 2 * MAT_BYTES + (b_row + np * 16) * RSTRIDE + ks * 32 + b_coff;
                ldsm_x4(bhf[np][0], bhf[np][1], bhf[np][2], bhf[np][3], baddr);
                ldsm_x4(blf[np][0], blf[np][1], blf[np][2], blf[np][3], baddr + MAT_BYTES);
            }
            MMA_BLOCK_128(acc, ah, al, bhf, blf);
        }
        if (kt < KT - 1) sstore((kt + 1) & 1);
        __syncthreads();
    }

    const int erow0 = m0 + warp_m * 32 + (l >> 2);
    const int ecol0 = n0 + warp_n * 64 + (l & 3) * 2;
    #pragma unroll
    for (int bm = 0; bm < 2; ++bm) {
        #pragma unroll
        for (int nb = 0; nb < 8; ++nb) {
            const int col = ecol0 + nb * 8;
            const float s0 = bnS[col], s1 = bnS[col + 1];
            const float v0 = bnB[col], v1 = bnB[col + 1];
            const int r0 = erow0 + bm * 16;
            float a0 = fmaxf(acc[bm][nb][0] * s0 + v0, 0.0f);
            float a1 = fmaxf(acc[bm][nb][1] * s1 + v1, 0.0f);
            float a2 = fmaxf(acc[bm][nb][2] * s0 + v0, 0.0f);
            float a3 = fmaxf(acc[bm][nb][3] * s1 + v1, 0.0f);
            uint32_t ph, pl;
            split2(a0, a1, ph, pl);
            *(uint32_t*)&g_yh[(size_t)r0 * ICH + col] = ph;
            *(uint32_t*)&g_yl[(size_t)r0 * ICH + col] = pl;
            split2(a2, a3, ph, pl);
            *(uint32_t*)&g_yh[(size_t)(r0 + 8) * ICH + col] = ph;
            *(uint32_t*)&g_yl[(size_t)(r0 + 8) * ICH + col] = pl;
        }
    }
}

// ---------------------------------------------------------------------------
// Kernel 2: 1x1 projections (M=8192, N=128, K=256)
// ---------------------------------------------------------------------------
__global__ __launch_bounds__(256, 1)
void proj_mma_kernel(const float* __restrict__ sf, const float* __restrict__ bf,
                     const float* __restrict__ ss, const float* __restrict__ bs,
                     const float* __restrict__ sg, const float* __restrict__ bg)
{
    extern __shared__ char smem[];
    const uint32_t sbase = smem_u32(smem);

    const int z = blockIdx.z;
    const __nv_bfloat16* Wh = (z == 0) ? g_wfh : (z == 1) ? g_wsh : g_wgh;
    const __nv_bfloat16* Wl = (z == 0) ? g_wfl : (z == 1) ? g_wsl : g_wgl;
    const float* Sv = (z == 0) ? sf : (z == 1) ? ss : sg;
    const float* Bv = (z == 0) ? bf : (z == 1) ? bs : bg;

    const int tid = threadIdx.x;
    const int wid = tid >> 5;
    const int l   = tid & 31;
    const int warp_m = wid & 3;
    const int warp_n = wid >> 2;
    const int m0 = blockIdx.x * 128;
    const int lr = tid >> 1;

    float acc[2][8][4];
    #pragma unroll
    for (int i = 0; i < 2; i++)
        #pragma unroll
        for (int j = 0; j < 8; j++)
            #pragma unroll
            for (int k = 0; k < 4; k++) acc[i][j][k] = 0.0f;

    uint4 ah2[2], al2[2], bh2[2], bl2[2];

    auto gload = [&](int kt) {
        const int kb = kt * 32;
        #pragma unroll
        for (int j = 0; j < 2; j++) {
            const int q4 = (tid & 1) * 2 + j;
            const int k = kb + q4 * 8;
            ah2[j] = *(const uint4*)&g_yh[(size_t)(m0 + lr) * ICH + k];
            al2[j] = *(const uint4*)&g_yl[(size_t)(m0 + lr) * ICH + k];
            bh2[j] = *(const uint4*)&Wh[(size_t)lr * ICH + k];
            bl2[j] = *(const uint4*)&Wl[(size_t)lr * ICH + k];
        }
    };
    auto sstore = [&](int stage) {
        char* sb = smem + stage * STAGE_BYTES;
        #pragma unroll
        for (int j = 0; j < 2; j++) {
            const int q4 = (tid & 1) * 2 + j;
            const uint32_t off4 = (uint32_t)(lr * RSTRIDE + q4 * 16);
            *(uint4*)(sb + off4) = ah2[j];
            *(uint4*)(sb + MAT_BYTES + off4) = al2[j];
            *(uint4*)(sb + 2 * MAT_BYTES + off4) = bh2[j];
            *(uint4*)(sb + 3 * MAT_BYTES + off4) = bl2[j];
        }
    };

    const uint32_t a_row = (uint32_t)(warp_m * 32 + (l & 15));
    const uint32_t a_coff = (uint32_t)((l >> 4) << 4);
    const uint32_t b_row = (uint32_t)(warp_n * 64 + (l & 7) + ((l >> 4) & 1) * 8);
    const uint32_t b_coff = (uint32_t)(((l >> 3) & 1) << 4);

    gload(0);
    sstore(0);
    __syncthreads();

    const int KT = ICH / 32;
    for (int kt = 0; kt < KT; ++kt) {
        if (kt < KT - 1) gload(kt + 1);
        const uint32_t st = sbase + (uint32_t)((kt & 1) * STAGE_BYTES);
        #pragma unroll
        for (int ks = 0; ks < 2; ++ks) {
            uint32_t ah[2][4], al[2][4], bhf[4][4], blf[4][4];
            #pragma unroll
            for (int bm = 0; bm < 2; ++bm) {
                const uint32_t aaddr = st + (a_row + bm * 16) * RSTRIDE + ks * 32 + a_coff;
                ldsm_x4(ah[bm][0], ah[bm][1], ah[bm][2], ah[bm][3], aaddr);
                ldsm_x4(al[bm][0], al[bm][1], al[bm][2], al[bm][3], aaddr + MAT_BYTES);
            }
            #pragma unroll
            for (int np = 0; np < 4; ++np) {
                const uint32_t baddr = st + 2 * MAT_BYTES + (b_row + np * 16) * RSTRIDE + ks * 32 + b_coff;
                ldsm_x4(bhf[np][0], bhf[np][1], bhf[np][2], bhf[np][3], baddr);
                ldsm_x4(blf[np][0], blf[np][1], blf[np][2], blf[np][3], baddr + MAT_BYTES);
            }
            MMA_BLOCK_128(acc, ah, al, bhf, blf);
        }
        if (kt < KT - 1) sstore((kt + 1) & 1);
        __syncthreads();
    }

    const int erow0 = m0 + warp_m * 32 + (l >> 2);
    const int ecol0 = warp_n * 64 + (l & 3) * 2;
    #pragma unroll
    for (int bm = 0; bm < 2; ++bm) {
        #pragma unroll
        for (int nb = 0; nb < 8; ++nb) {
            const int col = ecol0 + nb * 8;
            const float s0 = Sv[col], s1 = Sv[col + 1];
            const float v0 = Bv[col], v1 = Bv[col + 1];
            const int r0 = erow0 + bm * 16;
            float a0 = fmaxf(acc[bm][nb][0] * s0 + v0, 0.0f);
            float a1 = fmaxf(acc[bm][nb][1] * s1 + v1, 0.0f);
            float a2 = fmaxf(acc[bm][nb][2] * s0 + v0, 0.0f);
            float a3 = fmaxf(acc[bm][nb][3] * s1 + v1, 0.0f);
            if (z < 2) {
                __nv_bfloat16* Oh = (z == 0) ? g_faih : g_sith;
                __nv_bfloat16* Ol = (z == 0) ? g_fail_ : g_sitl;
                uint32_t ph, pl;
                split2(a0, a1, ph, pl);
                *(uint32_t*)&Oh[(size_t)r0 * NFC + col] = ph;
                *(uint32_t*)&Ol[(size_t)r0 * NFC + col] = pl;
                split2(a2, a3, ph, pl);
                *(uint32_t*)&Oh[(size_t)(r0 + 8) * NFC + col] = ph;
                *(uint32_t*)&Ol[(size_t)(r0 + 8) * NFC + col] = pl;
            } else {
                const int bb = r0 >> 10;
                const int n  = r0 & 1023;
                const size_t base = (size_t)bb * NFC * NPIX;
                float vals[4] = {a0, a1, a2, a3};
                const int cols[2] = {col, col + 1};
                const int rows[2] = {n, n + 8};
                #pragma unroll
                for (int ii = 0; ii < 4; ii++) {
                    const int cc = cols[ii & 1];
                    const int rr = rows[ii >> 1];
                    __nv_bfloat16 h = __float2bfloat16_rn(vals[ii]);
                    g_gTh[base + (size_t)cc * NPIX + rr] = h;
                    g_gTl[base + (size_t)cc * NPIX + rr] =
                        __float2bfloat16_rn(vals[ii] - __bfloat162float(h));
                }
            }
        }
    }
}

// ---------------------------------------------------------------------------
// Kernel 3: score S = sigmoid(fai . sit) (per batch M=N=1024, K=128)
// ---------------------------------------------------------------------------
__global__ __launch_bounds__(256, 1)
void score_mma_kernel()
{
    extern __shared__ char smem[];
    const uint32_t sbase = smem_u32(smem);

    const int b  = blockIdx.z;
    const int m0 = blockIdx.x * 128;
    const int n0 = blockIdx.y * 128;
    const int tid = threadIdx.x;
    const int wid = tid >> 5;
    const int l   = tid & 31;
    const int warp_m = wid & 3;
    const int warp_n = wid >> 2;
    const int lr = tid >> 1;

    const size_t abase = (size_t)b * NPIX * NFC;

    float acc[2][8][4];
    #pragma unroll
    for (int i = 0; i < 2; i++)
        #pragma unroll
        for (int j = 0; j < 8; j++)
            #pragma unroll
            for (int k = 0; k < 4; k++) acc[i][j][k] = 0.0f;

    uint4 ah2[2], al2[2], bh2[2], bl2[2];

    auto gload = [&](int kt) {
        const int kb = kt * 32;
        #pragma unroll
        for (int j = 0; j < 2; j++) {
            const int q4 = (tid & 1) * 2 + j;
            const int k = kb + q4 * 8;
            ah2[j] = *(const uint4*)&g_faih[abase + (size_t)(m0 + lr) * NFC + k];
            al2[j] = *(const uint4*)&g_fail_[abase + (size_t)(m0 + lr) * NFC + k];
            bh2[j] = *(const uint4*)&g_sith[abase + (size_t)(n0 + lr) * NFC + k];
            bl2[j] = *(const uint4*)&g_sitl[abase + (size_t)(n0 + lr) * NFC + k];
        }
    };
    auto sstore = [&](int stage) {
        char* sb = smem + stage * STAGE_BYTES;
        #pragma unroll
        for (int j = 0; j < 2; j++) {
            const int q4 = (tid & 1) * 2 + j;
            const uint32_t off4 = (uint32_t)(lr * RSTRIDE + q4 * 16);
            *(uint4*)(sb + off4) = ah2[j];
            *(uint4*)(sb + MAT_BYTES + off4) = al2[j];
            *(uint4*)(sb + 2 * MAT_BYTES + off4) = bh2[j];
            *(uint4*)(sb + 3 * MAT_BYTES + off4) = bl2[j];
        }
    };

    const uint32_t a_row = (uint32_t)(warp_m * 32 + (l & 15));
    const uint32_t a_coff = (uint32_t)((l >> 4) << 4);
    const uint32_t b_row = (uint32_t)(warp_n * 64 + (l & 7) + ((l >> 4) & 1) * 8);
    const uint32_t b_coff = (uint32_t)(((l >> 3) & 1) << 4);

    gload(0);
    sstore(0);
    __syncthreads();

    const int KT = NFC / 32;
    for (int kt = 0; kt < KT; ++kt) {
        if (kt < KT - 1) gload(kt + 1);
        const uint32_t st = sbase + (uint32_t)((kt & 1) * STAGE_BYTES);
        #pragma unroll
        for (int ks = 0; ks < 2; ++ks) {
            uint32_t ah[2][4], al[2][4], bhf[4][4], blf[4][4];
            #pragma unroll
            for (int bm = 0; bm < 2; ++bm) {
                const uint32_t aaddr = st + (a_row + bm * 16) * RSTRIDE + ks * 32 + a_coff;
                ldsm_x4(ah[bm][0], ah[bm][1], ah[bm][2], ah[bm][3], aaddr);
                ldsm_x4(al[bm][0], al[bm][1], al[bm][2], al[bm][3], aaddr + MAT_BYTES);
            }
            #pragma unroll
            for (int np = 0; np < 4; ++np) {
                const uint32_t baddr = st + 2 * MAT_BYTES + (b_row + np * 16) * RSTRIDE + ks * 32 + b_coff;
                ldsm_x4(bhf[np][0], bhf[np][1], bhf[np][2], bhf[np][3], baddr);
                ldsm_x4(blf[np][0], blf[np][1], blf[np][2], blf[np][3], baddr + MAT_BYTES);
            }
            MMA_BLOCK_128(acc, ah, al, bhf, blf);
        }
        if (kt < KT - 1) sstore((kt + 1) & 1);
        __syncthreads();
    }

    const size_t sb_out = (size_t)b * NPIX * NPIX;
    const int erow0 = m0 + warp_m * 32 + (l >> 2);
    const int ecol0 = n0 + warp_n * 64 + (l & 3) * 2;
    #pragma unroll
    for (int bm = 0; bm < 2; ++bm) {
        #pragma unroll
        for (int nb = 0; nb < 8; ++nb) {
            const int col = ecol0 + nb * 8;
            const int r0 = erow0 + bm * 16;
            float a0 = 1.0f / (1.0f + expf(-acc[bm][nb][0]));
            float a1 = 1.0f / (1.0f + expf(-acc[bm][nb][1]));
            float a2 = 1.0f / (1.0f + expf(-acc[bm][nb][2]));
            float a3 = 1.0f / (1.0f + expf(-acc[bm][nb][3]));
            uint32_t ph, pl;
            split2(a0, a1, ph, pl);
            *(uint32_t*)&g_Sh[sb_out + (size_t)r0 * NPIX + col] = ph;
            *(uint32_t*)&g_Sl[sb_out + (size_t)r0 * NPIX + col] = pl;
            split2(a2, a3, ph, pl);
            *(uint32_t*)&g_Sh[sb_out + (size_t)(r0 + 8) * NPIX + col] = ph;
            *(uint32_t*)&g_Sl[sb_out + (size_t)(r0 + 8) * NPIX + col] = pl;
        }
    }
}

// ---------------------------------------------------------------------------
// Kernel 4: att = S @ gamaT  (per batch M=1024 tile 64, N=128, K=1024)
// ---------------------------------------------------------------------------
#define AT_A_HI 0
#define AT_A_LO 5120
#define AT_B_HI 10240
#define AT_B_LO 20480
#define AT_STAGE 30720
#define AT_SMEM (2 * AT_STAGE)

__global__ __launch_bounds__(256, 1)
void attn_mma_kernel()
{
    extern __shared__ char smem[];
    const uint32_t sbase = smem_u32(smem);

    const int b  = blockIdx.z;
    const int m0 = blockIdx.x * 64;
    const int tid = threadIdx.x;
    const int wid = tid >> 5;
    const int l   = tid & 31;
    const int warp_m = wid & 1;
    const int warp_n = wid >> 1;

    const size_t sBase = (size_t)b * NPIX * NPIX;
    const size_t gBase = (size_t)b * NFC * NPIX;

    float acc[2][4][4];
    #pragma unroll
    for (int i = 0; i < 2; i++)
        #pragma unroll
        for (int j = 0; j < 4; j++)
            #pragma unroll
            for (int k = 0; k < 4; k++) acc[i][j][k] = 0.0f;

    uint4 ah1, al1, bh2[2], bl2[2];
    const int ar = tid >> 2;
    const int aq = tid & 3;
    const int br = tid >> 1;

    auto gload = [&](int kt) {
        const int kb = kt * 32;
        {
            const int k = kb + aq * 8;
            ah1 = *(const uint4*)&g_Sh[sBase + (size_t)(m0 + ar) * NPIX + k];
            al1 = *(const uint4*)&g_Sl[sBase + (size_t)(m0 + ar) * NPIX + k];
        }
        #pragma unroll
        for (int j = 0; j < 2; j++) {
            const int q4 = (tid & 1) * 2 + j;
            const int k = kb + q4 * 8;
            bh2[j] = *(const uint4*)&g_gTh[gBase + (size_t)br * NPIX + k];
            bl2[j] = *(const uint4*)&g_gTl[gBase + (size_t)br * NPIX + k];
        }
    };
    auto sstore = [&](int stage) {
        char* sb = smem + stage * AT_STAGE;
        {
            const uint32_t off = (uint32_t)(ar * RSTRIDE + aq * 16);
            *(uint4*)(sb + AT_A_HI + off) = ah1;
            *(uint4*)(sb + AT_A_LO + off) = al1;
        }
        #pragma unroll
        for (int j = 0; j < 2; j++) {
            const int q4 = (tid & 1) * 2 + j;
            const uint32_t off = (uint32_t)(br * RSTRIDE + q4 * 16);
            *(uint4*)(sb + AT_B_HI + off) = bh2[j];
            *(uint4*)(sb + AT_B_LO + off) = bl2[j];
        }
    };

    const uint32_t a_row = (uint32_t)(warp_m * 32 + (l & 15));
    const uint32_t a_coff = (uint32_t)((l >> 4) << 4);
    const uint32_t b_row = (uint32_t)(warp_n * 32 + (l & 7) + ((l >> 4) & 1) * 8);
    const uint32_t b_coff = (uint32_t)(((l >> 3) & 1) << 4);

    gload(0);
    sstore(0);
    __syncthreads();

    const int KT = NPIX / 32;
    for (int kt = 0; kt < KT; ++kt) {
        if (kt < KT - 1) gload(kt + 1);
        const uint32_t st = sbase + (uint32_t)((kt & 1) * AT_STAGE);
        #pragma unroll
        for (int ks = 0; ks < 2; ++ks) {
            uint32_t ah[2][4], al[2][4], bhf[2][4], blf[2][4];
            #pragma unroll
            for (int bm = 0; bm < 2; ++bm) {
                const uint32_t aaddr = st + AT_A_HI + (a_row + bm * 16) * RSTRIDE + ks * 32 + a_coff;
                ldsm_x4(ah[bm][0], ah[bm][1], ah[bm][2], ah[bm][3], aaddr);
                ldsm_x4(al[bm][0], al[bm][1], al[bm][2], al[bm][3], aaddr + (AT_A_LO - AT_A_HI));
            }
            #pragma unroll
            for (int np = 0; np < 2; ++np) {
                const uint32_t baddr = st + AT_B_HI + (b_row + np * 16) * RSTRIDE + ks * 32 + b_coff;
                ldsm_x4(bhf[np][0], bhf[np][1], bhf[np][2], bhf[np][3], baddr);
                ldsm_x4(blf[np][0], blf[np][1], blf[np][2], blf[np][3], baddr + (AT_B_LO - AT_B_HI));
            }
            #pragma unroll
            for (int np = 0; np < 2; ++np)
                #pragma unroll
                for (int bm = 0; bm < 2; ++bm) {
                    mma_bf16(acc[bm][np * 2],     ah[bm], bhf[np][0], bhf[np][1]);
                    mma_bf16(acc[bm][np * 2 + 1], ah[bm], bhf[np][2], bhf[np][3]);
                }
            #pragma unroll
            for (int np = 0; np < 2; ++np)
                #pragma unroll
                for (int bm = 0; bm < 2; ++bm) {
                    mma_bf16(acc[bm][np * 2],     al[bm], bhf[np][0], bhf[np][1]);
                    mma_bf16(acc[bm][np * 2 + 1], al[bm], bhf[np][2], bhf[np][3]);
                }
            #pragma unroll
            for (int np = 0; np < 2; ++np)
                #pragma unroll
                for (int bm = 0; bm < 2; ++bm) {
                    mma_bf16(acc[bm][np * 2],     ah[bm], blf[np][0], blf[np][1]);
                    mma_bf16(acc[bm][np * 2 + 1], ah[bm], blf[np][2], blf[np][3]);
                }
        }
        if (kt < KT - 1) sstore((kt + 1) & 1);
        __syncthreads();
    }

    const int erow0 = m0 + warp_m * 32 + (l >> 2);
    const int ecol0 = warp_n * 32 + (l & 3) * 2;
    #pragma unroll
    for (int bm = 0; bm < 2; ++bm) {
        #pragma unroll
        for (int nb = 0; nb < 4; ++nb) {
            const int col = ecol0 + nb * 8;
            const int r0 = erow0 + bm * 16;
            float2 o0 = {acc[bm][nb][0], acc[bm][nb][1]};
            float2 o1 = {acc[bm][nb][2], acc[bm][nb][3]};
            *(float2*)&g_att[((size_t)b * NPIX + r0) * NFC + col] = o0;
            *(float2*)&g_att[((size_t)b * NPIX + r0 + 8) * NFC + col] = o1;
        }
    }
}

// ---------------------------------------------------------------------------
// Kernel 5: bilinear upsample x8 (align_corners) with smem row staging
//   block = (b, c, ytile of 8 rows); 256 threads = 256 xo; 8 rows each
// ---------------------------------------------------------------------------
__global__ __launch_bounds__(256)
void upsample_kernel(float* __restrict__ out)
{
    __shared__ float rows[3][32];
    const int gx = blockIdx.x;
    const int yt = gx & 31;
    const int c  = (gx >> 5) & 127;
    const int b  = gx >> 12;
    const int t = threadIdx.x;

    const float sc = 31.0f / 255.0f;
    const int rbase = (int)floorf((float)(yt * 8) * sc);
    if (t < 96) {
        const int rr = t >> 5, xx = t & 31;
        const int r = min(rbase + rr, 31);
        rows[rr][xx] = g_att[((size_t)b * NPIX + r * 32 + xx) * NFC + c];
    }
    __syncthreads();

    const int xo = t;
    const float xs = (float)xo * sc;
    const int x0 = (int)floorf(xs);
    const float wx = xs - (float)x0;
    const int x1 = min(x0 + 1, 31);
    const size_t obase = ((size_t)(b * 128 + c)) * 256 * 256;

    #pragma unroll
    for (int i = 0; i < 8; ++i) {
        const int yo = yt * 8 + i;
        const float ysf = (float)yo * sc;
        const int y0 = (int)floorf(ysf);
        const float wy = ysf - (float)y0;
        const int y1 = min(y0 + 1, 31);
        const int r0 = y0 - rbase, r1 = y1 - rbase;
        const float v00 = rows[r0][x0], v01 = rows[r0][x1];
        const float v10 = rows[r1][x0], v11 = rows[r1][x1];
        const float top0 = v00 * (1.0f - wy) + v10 * wy;
        const float top1 = v01 * (1.0f - wy) + v11 * wy;
        out[obase + (size_t)yo * 256 + xo] = top0 * (1.0f - wx) + top1 * wx;
    }
}

// ---------------------------------------------------------------------------
// Launch
// ---------------------------------------------------------------------------
extern "C" void kernel_launch(void* const* d_in, const int* in_sizes, int n_in,
                              void* d_out, int out_size)
{
    const float* x     = (const float*)d_in[0];
    const float* w1    = (const float*)d_in[1];
    const float* bn1_s = (const float*)d_in[2];
    const float* bn1_b = (const float*)d_in[3];
    const float* w_fai = (const float*)d_in[4];
    const float* bnf_s = (const float*)d_in[5];
    const float* bnf_b = (const float*)d_in[6];
    const float* w_sit = (const float*)d_in[7];
    const float* bns_s = (const float*)d_in[8];
    const float* bns_b = (const float*)d_in[9];
    const float* w_gam = (const float*)d_in[10];
    const float* bng_s = (const float*)d_in[11];
    const float* bng_b = (const float*)d_in[12];
    float* out = (float*)d_out;

    static bool attr_done = false;
    if (!attr_done) {
        cudaFuncSetAttribute(conv1_mma_kernel, cudaFuncAttributeMaxDynamicSharedMemorySize, GEMM_SMEM);
        cudaFuncSetAttribute(proj_mma_kernel,  cudaFuncAttributeMaxDynamicSharedMemorySize, GEMM_SMEM);
        cudaFuncSetAttribute(score_mma_kernel, cudaFuncAttributeMaxDynamicSharedMemorySize, GEMM_SMEM);
        cudaFuncSetAttribute(attn_mma_kernel,  cudaFuncAttributeMaxDynamicSharedMemorySize, AT_SMEM);
        cudaFuncSetAttribute(im2col_kernel,    cudaFuncAttributeMaxDynamicSharedMemorySize, I2C_SMEM);
        attr_done = true;
    }

    // 0a. weight preconversion
    {
        const int total = ICH * KCONV + 3 * NFC * ICH;
        prep_kernel<<<(total + 255) / 256, 256>>>(w1, w_fai, w_sit, w_gam);
    }
    // 0b. im2col(x) -> bf16 hi/lo
    {
        im2col_kernel<<<2048, 256, I2C_SMEM>>>(x);
    }
    // 1. conv1 GEMM + BN + ReLU
    {
        dim3 grid(MROWS / 128, ICH / 128);
        conv1_mma_kernel<<<grid, 256, GEMM_SMEM>>>(bn1_s, bn1_b);
    }
    // 2. projections
    {
        dim3 grid(MROWS / 128, 1, 3);
        proj_mma_kernel<<<grid, 256, GEMM_SMEM>>>(bnf_s, bnf_b, bns_s, bns_b, bng_s, bng_b);
    }
    // 3. S = sigmoid(fai . sit)
    {
        dim3 grid(NPIX / 128, NPIX / 128, BATCH);
        score_mma_kernel<<<grid, 256, GEMM_SMEM>>>();
    }
    // 4. att = S @ gamaT
    {
        dim3 grid(NPIX / 64, 1, BATCH);
        attn_mma_kernel<<<grid, 256, AT_SMEM>>>();
    }
    // 5. upsample
    {
        upsample_kernel<<<BATCH * 128 * 32, 256>>>(out);
    }
}

// round 6
// speedup vs baseline: 2.4736x; 1.0472x over previous
#include <cuda_runtime.h>
#include <cuda_bf16.h>
#include <math.h>
#include <stdint.h>

// ---------------------------------------------------------------------------
// Problem constants
// ---------------------------------------------------------------------------
#define BATCH 8
#define ICH   256
#define NFC   128
#define NPIX  1024
#define KCONV 4096
#define MROWS 8192

// ---------------------------------------------------------------------------
// Device scratch (bf16 hi/lo split pairs throughout the GEMM chain)
// ---------------------------------------------------------------------------
__device__ __nv_bfloat16 g_w1h[ICH * KCONV], g_w1l[ICH * KCONV];
__device__ __nv_bfloat16 g_wfh[NFC * ICH],  g_wfl[NFC * ICH];
__device__ __nv_bfloat16 g_wsh[NFC * ICH],  g_wsl[NFC * ICH];
__device__ __nv_bfloat16 g_wgh[NFC * ICH],  g_wgl[NFC * ICH];

__device__ __nv_bfloat16 g_xh[MROWS * KCONV], g_xl[MROWS * KCONV];   // im2col(x)
__device__ __nv_bfloat16 g_yh[MROWS * ICH],  g_yl[MROWS * ICH];
__device__ __nv_bfloat16 g_faih[BATCH * NPIX * NFC], g_fail_[BATCH * NPIX * NFC];
__device__ __nv_bfloat16 g_sith[BATCH * NPIX * NFC], g_sitl[BATCH * NPIX * NFC];
__device__ __nv_bfloat16 g_gTh[BATCH * NFC * NPIX],  g_gTl[BATCH * NFC * NPIX];  // [b][c][m]
__device__ __nv_bfloat16 g_Sh[BATCH * NPIX * NPIX],  g_Sl[BATCH * NPIX * NPIX];  // [b][n][m]
__device__ float g_att0[BATCH * NPIX * NFC];   // split-K partials
__device__ float g_att1[BATCH * NPIX * NFC];

// ---------------------------------------------------------------------------
// Portable helpers (base sm_103)
// ---------------------------------------------------------------------------
__device__ __forceinline__ uint32_t smem_u32(const void* p) {
    uint32_t a;
    asm("{ .reg .u64 t; cvta.to.shared.u64 t, %1; cvt.u32.u64 %0, t; }" : "=r"(a) : "l"(p));
    return a;
}

__device__ __forceinline__ void cp16(uint32_t saddr, const void* gaddr) {
    asm volatile("cp.async.cg.shared.global [%0], [%1], 16;" :: "r"(saddr), "l"(gaddr));
}
#define CP_COMMIT() asm volatile("cp.async.commit_group;" ::: "memory")
#define CP_WAIT(n)  asm volatile("cp.async.wait_group %0;" :: "n"(n) : "memory")

__device__ __forceinline__ void ldsm_x4(uint32_t& r0, uint32_t& r1, uint32_t& r2, uint32_t& r3,
                                        uint32_t addr) {
    asm volatile("ldmatrix.sync.aligned.m8n8.x4.shared.b16 {%0,%1,%2,%3}, [%4];"
        : "=r"(r0), "=r"(r1), "=r"(r2), "=r"(r3) : "r"(addr));
}

__device__ __forceinline__ void mma_bf16(float* c, const uint32_t* a,
                                         uint32_t b0, uint32_t b1) {
    asm volatile(
        "mma.sync.aligned.m16n8k16.row.col.f32.bf16.bf16.f32 "
        "{%0,%1,%2,%3}, {%4,%5,%6,%7}, {%8,%9}, {%0,%1,%2,%3};"
        : "+f"(c[0]), "+f"(c[1]), "+f"(c[2]), "+f"(c[3])
        : "r"(a[0]), "r"(a[1]), "r"(a[2]), "r"(a[3]), "r"(b0), "r"(b1));
}

__device__ __forceinline__ void split2(float a, float b, uint32_t& ph, uint32_t& pl) {
    __nv_bfloat16 h0 = __float2bfloat16_rn(a), h1 = __float2bfloat16_rn(b);
    float ra = a - __bfloat162float(h0), rb = b - __bfloat162float(h1);
    __nv_bfloat16 l0 = __float2bfloat16_rn(ra), l1 = __float2bfloat16_rn(rb);
    ph = (uint32_t)__bfloat16_as_ushort(h0) | ((uint32_t)__bfloat16_as_ushort(h1) << 16);
    pl = (uint32_t)__bfloat16_as_ushort(l0) | ((uint32_t)__bfloat16_as_ushort(l1) << 16);
}

// ---------------------------------------------------------------------------
// Unified 128x64 GEMM tile (hi/lo split, cp.async double-buffered)
//   smem per stage: Ahi[128x32] Alo Bhi[64x32] Blo, row stride 80B
// ---------------------------------------------------------------------------
#define RSTRIDE 80
#define A_LO_OFF 10240
#define B_HI_OFF 20480
#define B_LO_OFF 25600
#define STG      30720
#define GEMM_SMEM2 (2 * STG)     // 61440

__device__ __forceinline__ void gemm_tile_128x64(
    const __nv_bfloat16* __restrict__ Ah, const __nv_bfloat16* __restrict__ Al, int lda,
    const __nv_bfloat16* __restrict__ Bh, const __nv_bfloat16* __restrict__ Bl, int ldb,
    int K, uint32_t sbase, float acc[2][4][4])
{
    const int tid = threadIdx.x;
    const int l = tid & 31;
    const int wid = tid >> 5;
    const int warp_m = wid & 3, warp_n = wid >> 2;
    const int arow = tid >> 2;     // 0..63
    const int q4   = tid & 3;

    const uint32_t a_row = (uint32_t)(warp_m * 32 + (l & 15));
    const uint32_t a_co  = (uint32_t)((l >> 4) << 4);
    const uint32_t b_row = (uint32_t)(warp_n * 32 + (l & 7) + ((l >> 4) & 1) * 8);
    const uint32_t b_co  = (uint32_t)(((l >> 3) & 1) << 4);

    // ---- stage issue (6 x cp16 per thread) ----
    auto issue = [&](int s, int kb) {
        const uint32_t st = sbase + (uint32_t)s * STG;
        #pragma unroll
        for (int j = 0; j < 2; ++j) {
            const int row = arow + j * 64;
            const uint32_t so = st + (uint32_t)(row * RSTRIDE + q4 * 16);
            cp16(so,            Ah + (size_t)row * lda + kb + q4 * 8);
            cp16(so + A_LO_OFF, Al + (size_t)row * lda + kb + q4 * 8);
        }
        const uint32_t so = st + B_HI_OFF + (uint32_t)(arow * RSTRIDE + q4 * 16);
        cp16(so,                         Bh + (size_t)arow * ldb + kb + q4 * 8);
        cp16(so + (B_LO_OFF - B_HI_OFF), Bl + (size_t)arow * ldb + kb + q4 * 8);
    };

    issue(0, 0);
    CP_COMMIT();

    const int KT = K >> 5;
    for (int kt = 0; kt < KT; ++kt) {
        if (kt + 1 < KT) {
            issue((kt + 1) & 1, (kt + 1) << 5);
            CP_COMMIT();
            CP_WAIT(1);
        } else {
            CP_WAIT(0);
        }
        __syncthreads();

        const uint32_t st = sbase + (uint32_t)((kt & 1) * STG);
        #pragma unroll
        for (int ks = 0; ks < 2; ++ks) {
            uint32_t ah[2][4], al[2][4], bh[2][4], bl[2][4];
            #pragma unroll
            for (int bm = 0; bm < 2; ++bm) {
                const uint32_t aaddr = st + (a_row + bm * 16) * RSTRIDE + ks * 32 + a_co;
                ldsm_x4(ah[bm][0], ah[bm][1], ah[bm][2], ah[bm][3], aaddr);
                ldsm_x4(al[bm][0], al[bm][1], al[bm][2], al[bm][3], aaddr + A_LO_OFF);
            }
            #pragma unroll
            for (int np = 0; np < 2; ++np) {
                const uint32_t baddr = st + B_HI_OFF + (b_row + np * 16) * RSTRIDE + ks * 32 + b_co;
                ldsm_x4(bh[np][0], bh[np][1], bh[np][2], bh[np][3], baddr);
                ldsm_x4(bl[np][0], bl[np][1], bl[np][2], bl[np][3], baddr + (B_LO_OFF - B_HI_OFF));
            }
            // variant-major issue (dependency distance 8)
            #pragma unroll
            for (int np = 0; np < 2; ++np)
                #pragma unroll
                for (int bm = 0; bm < 2; ++bm) {
                    mma_bf16(acc[bm][np * 2],     ah[bm], bh[np][0], bh[np][1]);
                    mma_bf16(acc[bm][np * 2 + 1], ah[bm], bh[np][2], bh[np][3]);
                }
            #pragma unroll
            for (int np = 0; np < 2; ++np)
                #pragma unroll
                for (int bm = 0; bm < 2; ++bm) {
                    mma_bf16(acc[bm][np * 2],     al[bm], bh[np][0], bh[np][1]);
                    mma_bf16(acc[bm][np * 2 + 1], al[bm], bh[np][2], bh[np][3]);
                }
            #pragma unroll
            for (int np = 0; np < 2; ++np)
                #pragma unroll
                for (int bm = 0; bm < 2; ++bm) {
                    mma_bf16(acc[bm][np * 2],     ah[bm], bl[np][0], bl[np][1]);
                    mma_bf16(acc[bm][np * 2 + 1], ah[bm], bl[np][2], bl[np][3]);
                }
        }
        __syncthreads();
    }
}

// ---------------------------------------------------------------------------
// Kernel 0a: weight preconversion
// ---------------------------------------------------------------------------
__global__ __launch_bounds__(256)
void prep_kernel(const float* __restrict__ w1, const float* __restrict__ wf,
                 const float* __restrict__ ws, const float* __restrict__ wg)
{
    const int idx = blockIdx.x * 256 + threadIdx.x;
    const int NW1 = ICH * KCONV;
    if (idx < NW1) {
        float v = w1[idx];
        __nv_bfloat16 h = __float2bfloat16_rn(v);
        g_w1h[idx] = h;
        g_w1l[idx] = __float2bfloat16_rn(v - __bfloat162float(h));
    } else {
        int j = idx - NW1;
        if (j >= 3 * NFC * ICH) return;
        const int which = j >> 15;
        const int e = j & 32767;
        float v = (which == 0 ? wf : which == 1 ? ws : wg)[e];
        __nv_bfloat16 h = __float2bfloat16_rn(v);
        __nv_bfloat16 l = __float2bfloat16_rn(v - __bfloat162float(h));
        if (which == 0)      { g_wfh[e] = h; g_wfl[e] = l; }
        else if (which == 1) { g_wsh[e] = h; g_wsl[e] = l; }
        else                 { g_wgh[e] = h; g_wgl[e] = l; }
    }
}

// ---------------------------------------------------------------------------
// Kernel 0b: im2col of x into bf16 hi/lo
// ---------------------------------------------------------------------------
#define I2C_RS 264
#define I2C_SMEM (2 * 64 * I2C_RS * 2)

__global__ __launch_bounds__(256, 1)
void im2col_kernel(const float* __restrict__ x)
{
    extern __shared__ char smraw[];
    __nv_bfloat16* sh = (__nv_bfloat16*)smraw;
    __nv_bfloat16* sl = (__nv_bfloat16*)(smraw + 64 * I2C_RS * 2);

    const int bx = blockIdx.x;
    const int icc = bx & 7;
    const int oh  = (bx >> 3) & 31;
    const int b   = bx >> 8;
    const int t = threadIdx.x;

    #pragma unroll
    for (int it = 0; it < 16; ++it) {
        const int f = t + it * 256;
        const int w4 = f & 63;
        const int kh = (f >> 6) & 7;
        const int i  = f >> 9;
        const float4 v = *(const float4*)&x[((size_t)(b * 64 + icc * 8 + i) * 256 + oh * 8 + kh) * 256 + w4 * 4];
        const int row = i * 8 + kh;
        __nv_bfloat16 h0 = __float2bfloat16_rn(v.x), h1 = __float2bfloat16_rn(v.y);
        __nv_bfloat16 h2 = __float2bfloat16_rn(v.z), h3 = __float2bfloat16_rn(v.w);
        sh[row * I2C_RS + w4 * 4 + 0] = h0;
        sh[row * I2C_RS + w4 * 4 + 1] = h1;
        sh[row * I2C_RS + w4 * 4 + 2] = h2;
        sh[row * I2C_RS + w4 * 4 + 3] = h3;
        sl[row * I2C_RS + w4 * 4 + 0] = __float2bfloat16_rn(v.x - __bfloat162float(h0));
        sl[row * I2C_RS + w4 * 4 + 1] = __float2bfloat16_rn(v.y - __bfloat162float(h1));
        sl[row * I2C_RS + w4 * 4 + 2] = __float2bfloat16_rn(v.z - __bfloat162float(h2));
        sl[row * I2C_RS + w4 * 4 + 3] = __float2bfloat16_rn(v.w - __bfloat162float(h3));
    }
    __syncthreads();

    #pragma unroll
    for (int it = 0; it < 8; ++it) {
        const int f = t + it * 256;
        const int kh = f & 7;
        const int i  = (f >> 3) & 7;
        const int ow = f >> 6;
        const int row = i * 8 + kh;
        const size_t r = (size_t)b * 1024 + oh * 32 + ow;
        const size_t kbase = (size_t)(icc * 8 + i) * 64 + kh * 8;
        *(uint4*)&g_xh[r * KCONV + kbase] = *(const uint4*)&sh[row * I2C_RS + ow * 8];
        *(uint4*)&g_xl[r * KCONV + kbase] = *(const uint4*)&sl[row * I2C_RS + ow * 8];
    }
}

// ---------------------------------------------------------------------------
// Kernel 1: conv1 GEMM (M=8192, N=256, K=4096); grid (64, 4)
// ---------------------------------------------------------------------------
__global__ __launch_bounds__(256, 2)
void conv1_mma_kernel(const float* __restrict__ bnS, const float* __restrict__ bnB)
{
    extern __shared__ char smem[];
    const uint32_t sbase = smem_u32(smem);

    const int m0 = blockIdx.x * 128;
    const int n0 = blockIdx.y * 64;

    float acc[2][4][4] = {};
    gemm_tile_128x64(g_xh + (size_t)m0 * KCONV, g_xl + (size_t)m0 * KCONV, KCONV,
                     g_w1h + (size_t)n0 * KCONV, g_w1l + (size_t)n0 * KCONV, KCONV,
                     KCONV, sbase, acc);

    const int wid = threadIdx.x >> 5, l = threadIdx.x & 31;
    const int erow0 = m0 + (wid & 3) * 32 + (l >> 2);
    const int ecol0 = n0 + (wid >> 2) * 32 + (l & 3) * 2;
    #pragma unroll
    for (int bm = 0; bm < 2; ++bm) {
        #pragma unroll
        for (int nb = 0; nb < 4; ++nb) {
            const int col = ecol0 + nb * 8;
            const float s0 = bnS[col], s1 = bnS[col + 1];
            const float v0 = bnB[col], v1 = bnB[col + 1];
            const int r0 = erow0 + bm * 16;
            float a0 = fmaxf(acc[bm][nb][0] * s0 + v0, 0.0f);
            float a1 = fmaxf(acc[bm][nb][1] * s1 + v1, 0.0f);
            float a2 = fmaxf(acc[bm][nb][2] * s0 + v0, 0.0f);
            float a3 = fmaxf(acc[bm][nb][3] * s1 + v1, 0.0f);
            uint32_t ph, pl;
            split2(a0, a1, ph, pl);
            *(uint32_t*)&g_yh[(size_t)r0 * ICH + col] = ph;
            *(uint32_t*)&g_yl[(size_t)r0 * ICH + col] = pl;
            split2(a2, a3, ph, pl);
            *(uint32_t*)&g_yh[(size_t)(r0 + 8) * ICH + col] = ph;
            *(uint32_t*)&g_yl[(size_t)(r0 + 8) * ICH + col] = pl;
        }
    }
}

// ---------------------------------------------------------------------------
// Kernel 2: projections (M=8192, N=128->2 tiles, K=256); grid (64, 2, 3)
// ---------------------------------------------------------------------------
__global__ __launch_bounds__(256, 2)
void proj_mma_kernel(const float* __restrict__ sf, const float* __restrict__ bf,
                     const float* __restrict__ ss, const float* __restrict__ bs,
                     const float* __restrict__ sg, const float* __restrict__ bg)
{
    extern __shared__ char smem[];
    const uint32_t sbase = smem_u32(smem);

    const int z = blockIdx.z;
    const __nv_bfloat16* Wh = (z == 0) ? g_wfh : (z == 1) ? g_wsh : g_wgh;
    const __nv_bfloat16* Wl = (z == 0) ? g_wfl : (z == 1) ? g_wsl : g_wgl;
    const float* Sv = (z == 0) ? sf : (z == 1) ? ss : sg;
    const float* Bv = (z == 0) ? bf : (z == 1) ? bs : bg;

    const int m0 = blockIdx.x * 128;
    const int n0 = blockIdx.y * 64;

    float acc[2][4][4] = {};
    gemm_tile_128x64(g_yh + (size_t)m0 * ICH, g_yl + (size_t)m0 * ICH, ICH,
                     Wh + (size_t)n0 * ICH, Wl + (size_t)n0 * ICH, ICH,
                     ICH, sbase, acc);

    const int wid = threadIdx.x >> 5, l = threadIdx.x & 31;
    const int erow0 = m0 + (wid & 3) * 32 + (l >> 2);
    const int ecol0 = n0 + (wid >> 2) * 32 + (l & 3) * 2;
    #pragma unroll
    for (int bm = 0; bm < 2; ++bm) {
        #pragma unroll
        for (int nb = 0; nb < 4; ++nb) {
            const int col = ecol0 + nb * 8;
            const float s0 = Sv[col], s1 = Sv[col + 1];
            const float v0 = Bv[col], v1 = Bv[col + 1];
            const int r0 = erow0 + bm * 16;
            float a0 = fmaxf(acc[bm][nb][0] * s0 + v0, 0.0f);
            float a1 = fmaxf(acc[bm][nb][1] * s1 + v1, 0.0f);
            float a2 = fmaxf(acc[bm][nb][2] * s0 + v0, 0.0f);
            float a3 = fmaxf(acc[bm][nb][3] * s1 + v1, 0.0f);
            if (z < 2) {
                __nv_bfloat16* Oh = (z == 0) ? g_faih : g_sith;
                __nv_bfloat16* Ol = (z == 0) ? g_fail_ : g_sitl;
                uint32_t ph, pl;
                split2(a0, a1, ph, pl);
                *(uint32_t*)&Oh[(size_t)r0 * NFC + col] = ph;
                *(uint32_t*)&Ol[(size_t)r0 * NFC + col] = pl;
                split2(a2, a3, ph, pl);
                *(uint32_t*)&Oh[(size_t)(r0 + 8) * NFC + col] = ph;
                *(uint32_t*)&Ol[(size_t)(r0 + 8) * NFC + col] = pl;
            } else {
                const int bb = r0 >> 10;
                const int n  = r0 & 1023;
                const size_t base = (size_t)bb * NFC * NPIX;
                float vals[4] = {a0, a1, a2, a3};
                #pragma unroll
                for (int ii = 0; ii < 4; ii++) {
                    const int cc = col + (ii & 1);
                    const int rr = n + (ii >> 1) * 8;
                    __nv_bfloat16 h = __float2bfloat16_rn(vals[ii]);
                    g_gTh[base + (size_t)cc * NPIX + rr] = h;
                    g_gTl[base + (size_t)cc * NPIX + rr] =
                        __float2bfloat16_rn(vals[ii] - __bfloat162float(h));
                }
            }
        }
    }
}

// ---------------------------------------------------------------------------
// Kernel 3: score S = sigmoid(fai . sit); grid (8, 16, 8)
// ---------------------------------------------------------------------------
__global__ __launch_bounds__(256, 2)
void score_mma_kernel()
{
    extern __shared__ char smem[];
    const uint32_t sbase = smem_u32(smem);

    const int b  = blockIdx.z;
    const int m0 = blockIdx.x * 128;
    const int n0 = blockIdx.y * 64;
    const size_t abase = (size_t)b * NPIX * NFC;

    float acc[2][4][4] = {};
    gemm_tile_128x64(g_faih + abase + (size_t)m0 * NFC, g_fail_ + abase + (size_t)m0 * NFC, NFC,
                     g_sith + abase + (size_t)n0 * NFC, g_sitl + abase + (size_t)n0 * NFC, NFC,
                     NFC, sbase, acc);

    const size_t sb_out = (size_t)b * NPIX * NPIX;
    const int wid = threadIdx.x >> 5, l = threadIdx.x & 31;
    const int erow0 = m0 + (wid & 3) * 32 + (l >> 2);
    const int ecol0 = n0 + (wid >> 2) * 32 + (l & 3) * 2;
    #pragma unroll
    for (int bm = 0; bm < 2; ++bm) {
        #pragma unroll
        for (int nb = 0; nb < 4; ++nb) {
            const int col = ecol0 + nb * 8;
            const int r0 = erow0 + bm * 16;
            float a0 = 1.0f / (1.0f + expf(-acc[bm][nb][0]));
            float a1 = 1.0f / (1.0f + expf(-acc[bm][nb][1]));
            float a2 = 1.0f / (1.0f + expf(-acc[bm][nb][2]));
            float a3 = 1.0f / (1.0f + expf(-acc[bm][nb][3]));
            uint32_t ph, pl;
            split2(a0, a1, ph, pl);
            *(uint32_t*)&g_Sh[sb_out + (size_t)r0 * NPIX + col] = ph;
            *(uint32_t*)&g_Sl[sb_out + (size_t)r0 * NPIX + col] = pl;
            split2(a2, a3, ph, pl);
            *(uint32_t*)&g_Sh[sb_out + (size_t)(r0 + 8) * NPIX + col] = ph;
            *(uint32_t*)&g_Sl[sb_out + (size_t)(r0 + 8) * NPIX + col] = pl;
        }
    }
}

// ---------------------------------------------------------------------------
// Kernel 4: att = S @ gamaT, split-K(2); grid (8, 2, 16)
//   z = b*2 + kslice; partials to g_att0 / g_att1 (summed by upsample)
// ---------------------------------------------------------------------------
__global__ __launch_bounds__(256, 2)
void attn_mma_kernel()
{
    extern __shared__ char smem[];
    const uint32_t sbase = smem_u32(smem);

    const int z  = blockIdx.z;
    const int b  = z >> 1;
    const int ks = z & 1;
    const int m0 = blockIdx.x * 128;
    const int n0 = blockIdx.y * 64;
    const size_t sBase = (size_t)b * NPIX * NPIX;
    const size_t gBase = (size_t)b * NFC * NPIX;
    const int kofs = ks * 512;

    float acc[2][4][4] = {};
    gemm_tile_128x64(g_Sh + sBase + (size_t)m0 * NPIX + kofs,
                     g_Sl + sBase + (size_t)m0 * NPIX + kofs, NPIX,
                     g_gTh + gBase + (size_t)n0 * NPIX + kofs,
                     g_gTl + gBase + (size_t)n0 * NPIX + kofs, NPIX,
                     512, sbase, acc);

    float* outp = ks ? g_att1 : g_att0;
    const int wid = threadIdx.x >> 5, l = threadIdx.x & 31;
    const int erow0 = m0 + (wid & 3) * 32 + (l >> 2);
    const int ecol0 = n0 + (wid >> 2) * 32 + (l & 3) * 2;
    #pragma unroll
    for (int bm = 0; bm < 2; ++bm) {
        #pragma unroll
        for (int nb = 0; nb < 4; ++nb) {
            const int col = ecol0 + nb * 8;
            const int r0 = erow0 + bm * 16;
            float2 o0 = {acc[bm][nb][0], acc[bm][nb][1]};
            float2 o1 = {acc[bm][nb][2], acc[bm][nb][3]};
            *(float2*)&outp[((size_t)b * NPIX + r0) * NFC + col] = o0;
            *(float2*)&outp[((size_t)b * NPIX + r0 + 8) * NFC + col] = o1;
        }
    }
}

// ---------------------------------------------------------------------------
// Kernel 5: bilinear upsample x8 (align_corners), sums split-K partials
// ---------------------------------------------------------------------------
__global__ __launch_bounds__(256)
void upsample_kernel(float* __restrict__ out)
{
    __shared__ float rows[3][32];
    const int gx = blockIdx.x;
    const int yt = gx & 31;
    const int c  = (gx >> 5) & 127;
    const int b  = gx >> 12;
    const int t = threadIdx.x;

    const float sc = 31.0f / 255.0f;
    const int rbase = (int)floorf((float)(yt * 8) * sc);
    if (t < 96) {
        const int rr = t >> 5, xx = t & 31;
        const int r = min(rbase + rr, 31);
        const size_t idx = ((size_t)b * NPIX + r * 32 + xx) * NFC + c;
        rows[rr][xx] = g_att0[idx] + g_att1[idx];
    }
    __syncthreads();

    const int xo = t;
    const float xs = (float)xo * sc;
    const int x0 = (int)floorf(xs);
    const float wx = xs - (float)x0;
    const int x1 = min(x0 + 1, 31);
    const size_t obase = ((size_t)(b * 128 + c)) * 256 * 256;

    #pragma unroll
    for (int i = 0; i < 8; ++i) {
        const int yo = yt * 8 + i;
        const float ysf = (float)yo * sc;
        const int y0 = (int)floorf(ysf);
        const float wy = ysf - (float)y0;
        const int y1 = min(y0 + 1, 31);
        const int r0 = y0 - rbase, r1 = y1 - rbase;
        const float v00 = rows[r0][x0], v01 = rows[r0][x1];
        const float v10 = rows[r1][x0], v11 = rows[r1][x1];
        const float top0 = v00 * (1.0f - wy) + v10 * wy;
        const float top1 = v01 * (1.0f - wy) + v11 * wy;
        out[obase + (size_t)yo * 256 + xo] = top0 * (1.0f - wx) + top1 * wx;
    }
}

// ---------------------------------------------------------------------------
// Launch
// ---------------------------------------------------------------------------
extern "C" void kernel_launch(void* const* d_in, const int* in_sizes, int n_in,
                              void* d_out, int out_size)
{
    const float* x     = (const float*)d_in[0];
    const float* w1    = (const float*)d_in[1];
    const float* bn1_s = (const float*)d_in[2];
    const float* bn1_b = (const float*)d_in[3];
    const float* w_fai = (const float*)d_in[4];
    const float* bnf_s = (const float*)d_in[5];
    const float* bnf_b = (const float*)d_in[6];
    const float* w_sit = (const float*)d_in[7];
    const float* bns_s = (const float*)d_in[8];
    const float* bns_b = (const float*)d_in[9];
    const float* w_gam = (const float*)d_in[10];
    const float* bng_s = (const float*)d_in[11];
    const float* bng_b = (const float*)d_in[12];
    float* out = (float*)d_out;

    static bool attr_done = false;
    if (!attr_done) {
        cudaFuncSetAttribute(conv1_mma_kernel, cudaFuncAttributeMaxDynamicSharedMemorySize, GEMM_SMEM2);
        cudaFuncSetAttribute(proj_mma_kernel,  cudaFuncAttributeMaxDynamicSharedMemorySize, GEMM_SMEM2);
        cudaFuncSetAttribute(score_mma_kernel, cudaFuncAttributeMaxDynamicSharedMemorySize, GEMM_SMEM2);
        cudaFuncSetAttribute(attn_mma_kernel,  cudaFuncAttributeMaxDynamicSharedMemorySize, GEMM_SMEM2);
        cudaFuncSetAttribute(im2col_kernel,    cudaFuncAttributeMaxDynamicSharedMemorySize, I2C_SMEM);
        attr_done = true;
    }

    // 0a. weight preconversion
    {
        const int total = ICH * KCONV + 3 * NFC * ICH;
        prep_kernel<<<(total + 255) / 256, 256>>>(w1, w_fai, w_sit, w_gam);
    }
    // 0b. im2col(x) -> bf16 hi/lo
    im2col_kernel<<<2048, 256, I2C_SMEM>>>(x);
    // 1. conv1 GEMM + BN + ReLU
    {
        dim3 grid(MROWS / 128, ICH / 64);
        conv1_mma_kernel<<<grid, 256, GEMM_SMEM2>>>(bn1_s, bn1_b);
    }
    // 2. projections
    {
        dim3 grid(MROWS / 128, NFC / 64, 3);
        proj_mma_kernel<<<grid, 256, GEMM_SMEM2>>>(bnf_s, bnf_b, bns_s, bns_b, bng_s, bng_b);
    }
    // 3. S = sigmoid(fai . sit)
    {
        dim3 grid(NPIX / 128, NPIX / 64, BATCH);
        score_mma_kernel<<<grid, 256, GEMM_SMEM2>>>();
    }
    // 4. att = S @ gamaT (split-K 2)
    {
        dim3 grid(NPIX / 128, NFC / 64, BATCH * 2);
        attn_mma_kernel<<<grid, 256, GEMM_SMEM2>>>();
    }
    // 5. upsample (+ split-K reduce)
    upsample_kernel<<<BATCH * 128 * 32, 256>>>(out);
}